// round 9
// baseline (speedup 1.0000x reference)
#include <cuda_runtime.h>
#include <math.h>

// Problem constants
#define BB 8
#define NN 2048
#define PTS (BB*NN)      // 16384
#define DD 64
#define KK 8
#define LV 3
#define H1 256
#define H2 128
#define PTB 32           // points per k_fuse block
#define NZONE 4          // KNN j-zones

// Scratch (device globals; no allocation allowed)
__device__ float g_A  [PTS*DD];
__device__ float g_Bf [PTS*DD];
__device__ float g_fw [PTS*LV];
__device__ int   g_idx[PTS*KK];
__device__ float g_me [PTS*NZONE*KK];
__device__ int   g_mi [PTS*NZONE*KK];

__device__ __forceinline__ float leaky(float v){ return v > 0.f ? v : 0.2f*v; }

__device__ __forceinline__ unsigned long long ffma2(unsigned long long a, unsigned long long b, unsigned long long c){
    asm("fma.rn.f32x2 %0, %1, %2, %0;" : "+l"(c) : "l"(a), "l"(b));
    return c;
}
__device__ __forceinline__ unsigned long long pack2(float w){
    unsigned long long r;
    asm("mov.b64 %0, {%1, %1};" : "=l"(r) : "f"(w));
    return r;
}
__device__ __forceinline__ unsigned long long dbits(double d){ return __double_as_longlong(d); }

// ---------------------------------------------------------------------------
// K1: per-point prep, 128 points/block, grid 128.
//     feat = leaky((x@W1+b1)*g1+be1);
//     A = feat@W2[:64] + b2 ; Bf = feat@W2[64:] ;
//     fw = sigmoid(relu(x@Ws1+bs1)@Ws2+bs2)
// ---------------------------------------------------------------------------
__global__ void k_prep(const float* __restrict__ x,
                       const float* __restrict__ W1, const float* __restrict__ b1,
                       const float* __restrict__ g1, const float* __restrict__ be1,
                       const float* __restrict__ W2, const float* __restrict__ b2,
                       const float* __restrict__ Ws1, const float* __restrict__ bs1,
                       const float* __restrict__ Ws2, const float* __restrict__ bs2)
{
    extern __shared__ float sm[];
    float* W2s   = sm;               // 8192
    float* featS = sm + 8192;        // 128*65 = 8320
    float* ssS   = sm + 16512;       // 128*64 = 8192
    float* W1s   = sm + 24704;       // 192
    float* Ws1s  = sm + 24896;       // 192
    float* Ws2s  = sm + 25088;       // 192
    float* b1v   = sm + 25280;       // 64
    float* g1v   = sm + 25344;
    float* be1v  = sm + 25408;
    float* b2v   = sm + 25472;
    float* bs1v  = sm + 25536;
    float* bs2v  = sm + 25600;       // 4
    float* xs    = sm + 25604;       // 384  -> total 25988 floats

    const int tid = threadIdx.x;
    const int p0  = blockIdx.x * 128;

    for (int i = tid; i < 8192; i += 256) W2s[i] = W2[i];
    for (int i = tid; i < 192; i += 256) { W1s[i] = W1[i]; Ws1s[i] = Ws1[i]; Ws2s[i] = Ws2[i]; }
    for (int i = tid; i < 384; i += 256) xs[i] = x[p0*3 + i];
    if (tid < 64) { b1v[tid]=b1[tid]; g1v[tid]=g1[tid]; be1v[tid]=be1[tid]; b2v[tid]=b2[tid]; bs1v[tid]=bs1[tid]; }
    if (tid < 3)  bs2v[tid] = bs2[tid];
    __syncthreads();

    for (int i = tid; i < 8192; i += 256) {
        int pt = i >> 6, d = i & 63;
        float x0 = xs[pt*3], x1 = xs[pt*3+1], x2 = xs[pt*3+2];
        float f = fmaf(x2, W1s[128+d], fmaf(x1, W1s[64+d], fmaf(x0, W1s[d], b1v[d])));
        f = fmaf(f, g1v[d], be1v[d]);
        featS[pt*65 + d] = leaky(f);
        float s = fmaf(x2, Ws1s[128+d], fmaf(x1, Ws1s[64+d], fmaf(x0, Ws1s[d], bs1v[d])));
        ssS[pt*64 + d] = s > 0.f ? s : 0.f;
    }
    __syncthreads();

    for (int i = tid; i < 384; i += 256) {
        int pt = i / 3, l = i - pt*3;
        float s = bs2v[l];
        #pragma unroll 8
        for (int d = 0; d < 64; d++) s = fmaf(ssS[pt*64 + d], Ws2s[d*3 + l], s);
        g_fw[(p0+pt)*3 + l] = 1.f / (1.f + expf(-s));
    }

    // A / Bf : thread = (pt 0..127, grp 0..1 of 32 output dims); FFMA2-paired
    {
        int pt  = tid & 127;
        int grp = tid >> 7;
        unsigned long long accA[16], accB[16];
        #pragma unroll
        for (int u = 0; u < 16; u++) {
            accA[u] = *(const unsigned long long*)(b2v + grp*32 + 2*u);
            accB[u] = 0ull;
        }
        #pragma unroll 2
        for (int d = 0; d < 64; d++) {
            unsigned long long fv2 = pack2(featS[pt*65 + d]);
            const double2* wa = (const double2*)(W2s + d*64       + grp*32);
            const double2* wb = (const double2*)(W2s + (64+d)*64  + grp*32);
            #pragma unroll
            for (int u = 0; u < 8; u++) {
                double2 qa = wa[u], qb = wb[u];
                accA[2*u]   = ffma2(dbits(qa.x), fv2, accA[2*u]);
                accA[2*u+1] = ffma2(dbits(qa.y), fv2, accA[2*u+1]);
                accB[2*u]   = ffma2(dbits(qb.x), fv2, accB[2*u]);
                accB[2*u+1] = ffma2(dbits(qb.y), fv2, accB[2*u+1]);
            }
        }
        float2* pA = (float2*)(g_A  + (p0+pt)*64 + grp*32);
        float2* pB = (float2*)(g_Bf + (p0+pt)*64 + grp*32);
        #pragma unroll
        for (int u = 0; u < 16; u++) {
            pA[u] = *(float2*)&accA[u];
            pB[u] = *(float2*)&accB[u];
        }
    }
}

// ---------------------------------------------------------------------------
// K2: KNN zone pass. grid (32, 8, NZONE): 64 points/block, zone = 512 j's.
// e_j = xj.n - 2*(xi . xj)  (rank-equivalent to d2 for fixed i).
// SoA f32x2 packed distances: per 4 j: 4 LDS.128 + 6 FFMA2 + 3 FMNMX + sieve.
// Zone top-8 (by (e, idx) lexicographic) -> g_me/g_mi.
// ---------------------------------------------------------------------------
__global__ void k_knn(const float* __restrict__ x)
{
    __shared__ __align__(16) float xs0[512];
    __shared__ __align__(16) float xs1[512];
    __shared__ __align__(16) float xs2[512];
    __shared__ __align__(16) float xsw[512];
    __shared__ float md[64*33];
    __shared__ int   mi[64*33];

    const int tid   = threadIdx.x;
    const int b     = blockIdx.y;
    const int pl0   = blockIdx.x * 64;
    const int z     = blockIdx.z;
    const int jbase = z * 512;

    for (int j = tid; j < 512; j += 256) {
        const float* xp = x + (b*NN + jbase + j)*3;
        float x0 = xp[0], x1 = xp[1], x2 = xp[2];
        xs0[j] = x0; xs1[j] = x1; xs2[j] = x2;
        xsw[j] = fmaf(x2, x2, fmaf(x1, x1, x0*x0));
    }
    __syncthreads();

    const int pt = tid & 63, split = tid >> 6;
    const float* xi = x + (b*NN + pl0 + pt)*3;
    unsigned long long aa2 = pack2(-2.f * xi[0]);
    unsigned long long bb2 = pack2(-2.f * xi[1]);
    unsigned long long cc2 = pack2(-2.f * xi[2]);

    float bd[8]; int bi[8];
    #pragma unroll
    for (int s = 0; s < 8; s++) { bd[s] = 3.4e38f; bi[s] = 0x7fffffff; }

#define KNN_INS(dv, jv)                                                        \
    if ((dv) < bd[7]) {                                                        \
        int pos = 7;                                                           \
        _Pragma("unroll")                                                      \
        for (int s = 6; s >= 0; s--) if ((dv) < bd[s]) pos = s;                \
        _Pragma("unroll")                                                      \
        for (int s = 7; s >= 1; s--) if (s > pos) { bd[s] = bd[s-1]; bi[s] = bi[s-1]; } \
        bd[pos] = (dv); bi[pos] = (jv);                                        \
    }

    const int j0 = split * 128;          // local to zone
    const double2* X0 = (const double2*)(xs0 + j0);
    const double2* X1 = (const double2*)(xs1 + j0);
    const double2* X2 = (const double2*)(xs2 + j0);
    const double2* XW = (const double2*)(xsw + j0);
    #pragma unroll 2
    for (int v = 0; v < 32; v++) {       // 4 j's per iteration
        double2 p0 = X0[v], p1 = X1[v], p2 = X2[v], pw = XW[v];
        unsigned long long ea2 = dbits(pw.x);
        ea2 = ffma2(dbits(p2.x), cc2, ea2);
        ea2 = ffma2(dbits(p1.x), bb2, ea2);
        ea2 = ffma2(dbits(p0.x), aa2, ea2);
        unsigned long long eb2 = dbits(pw.y);
        eb2 = ffma2(dbits(p2.y), cc2, eb2);
        eb2 = ffma2(dbits(p1.y), bb2, eb2);
        eb2 = ffma2(dbits(p0.y), aa2, eb2);
        float2 ea = *(float2*)&ea2;
        float2 eb = *(float2*)&eb2;
        float m = fminf(fminf(ea.x, ea.y), fminf(eb.x, eb.y));
        if (m < bd[7]) {                 // rare; inserts preserve ascending order
            int jg = jbase + j0 + 4*v;
            KNN_INS(ea.x, jg);
            KNN_INS(ea.y, jg+1);
            KNN_INS(eb.x, jg+2);
            KNN_INS(eb.y, jg+3);
        }
    }
#undef KNN_INS

    #pragma unroll
    for (int s = 0; s < 8; s++) { md[pt*33 + split*8 + s] = bd[s]; mi[pt*33 + split*8 + s] = bi[s]; }
    __syncthreads();

    if (tid < 64) {
        float fd[8]; int fi[8];
        #pragma unroll
        for (int s = 0; s < 8; s++) { fd[s] = 3.4e38f; fi[s] = 0x7fffffff; }
        for (int c = 0; c < 32; c++) {
            float cd = md[tid*33 + c]; int ci = mi[tid*33 + c];
            bool ins = (cd < fd[7]) || (cd == fd[7] && ci < fi[7]);
            if (ins) {
                int pos = 7;
                #pragma unroll
                for (int s = 6; s >= 0; s--) if (cd < fd[s] || (cd == fd[s] && ci < fi[s])) pos = s;
                #pragma unroll
                for (int s = 7; s >= 1; s--) if (s > pos) { fd[s] = fd[s-1]; fi[s] = fi[s-1]; }
                fd[pos] = cd; fi[pos] = ci;
            }
        }
        int gp = b*NN + pl0 + tid;
        #pragma unroll
        for (int s = 0; s < 8; s++) {
            g_me[gp*32 + z*8 + s] = fd[s];
            g_mi[gp*32 + z*8 + s] = fi[s];
        }
    }
}

// ---------------------------------------------------------------------------
// K2b: merge NZONE zone-lists (each sorted-8) per point -> final top-8 idx.
// ---------------------------------------------------------------------------
__global__ void k_merge()
{
    int p = blockIdx.x * 256 + threadIdx.x;
    float ce[32]; int cidx[32];
    #pragma unroll
    for (int u = 0; u < 8; u++) {
        float4 v = *(const float4*)(g_me + p*32 + 4*u);
        int4   w = *(const int4*)  (g_mi + p*32 + 4*u);
        ce[4*u]=v.x; ce[4*u+1]=v.y; ce[4*u+2]=v.z; ce[4*u+3]=v.w;
        cidx[4*u]=w.x; cidx[4*u+1]=w.y; cidx[4*u+2]=w.z; cidx[4*u+3]=w.w;
    }
    float fd[8]; int fi[8];
    #pragma unroll
    for (int s = 0; s < 8; s++) { fd[s] = 3.4e38f; fi[s] = 0x7fffffff; }
    #pragma unroll
    for (int c = 0; c < 32; c++) {
        float cd = ce[c]; int ci = cidx[c];
        bool ins = (cd < fd[7]) || (cd == fd[7] && ci < fi[7]);
        if (ins) {
            int pos = 7;
            #pragma unroll
            for (int s = 6; s >= 0; s--) if (cd < fd[s] || (cd == fd[s] && ci < fi[s])) pos = s;
            #pragma unroll
            for (int s = 7; s >= 1; s--) if (s > pos) { fd[s] = fd[s-1]; fi[s] = fi[s-1]; }
            fd[pos] = cd; fi[pos] = ci;
        }
    }
    #pragma unroll
    for (int s = 0; s < 8; s++) g_idx[p*8 + s] = fi[s];
}

// ---------------------------------------------------------------------------
// K3 (fused): gather+edge-max+fw -> multiT (smem), then fusion MLP.
// 32 points/block, 256 threads, ~101.8KB smem -> 2 blocks/SM.
// ---------------------------------------------------------------------------
__global__ void __launch_bounds__(256, 2)
k_fuse(const float* __restrict__ x,
       const float* __restrict__ g2, const float* __restrict__ be2,
       const float* __restrict__ Wf1, const float* __restrict__ bf1,
       const float* __restrict__ gf1, const float* __restrict__ bef1,
       const float* __restrict__ Wf2, const float* __restrict__ bf2,
       const float* __restrict__ gf2, const float* __restrict__ bef2,
       const float* __restrict__ Wf3, const float* __restrict__ bf3,
       float* __restrict__ out)
{
    extern __shared__ float sm[];
    float* multiT = sm;                   // [192][34] = 6528 ; h2T aliases [128][34]
    float* h2T    = sm;
    float* h1T    = sm + 6528;            // [256][34] = 8704
    float* ws     = sm + 15232;           // 2 x 4096 = 8192
    float* b1S    = sm + 23424;           // 256
    float* g1S    = b1S + 256;            // 256
    float* e1S    = g1S + 256;            // 256
    float* b2S    = sm + 24192;           // 128
    float* g2S    = b2S + 128;            // 128
    float* e2S    = g2S + 128;            // 128
    float* wf3S   = sm + 24576;           // 384
    float* fwS    = sm + 24960;           // 96
    float* bf3S   = sm + 25056;           // 4
    int*   idxS   = (int*)(sm + 25060);   // 256
    float* g2v    = sm + 25316;           // 64
    float* be2v   = g2v + 64;             // 64   -> total 25444 floats

    const int tid  = threadIdx.x;
    const int lane = tid & 31;
    const int wrp  = tid >> 5;
    const int p0   = blockIdx.x * PTB;
    const int pg   = wrp & 3;
    const int oh   = wrp >> 2;
    const int pbase = pg * 8;

    { b1S[tid]=bf1[tid]; g1S[tid]=gf1[tid]; e1S[tid]=bef1[tid]; }
    if (tid < 128) { b2S[tid]=bf2[tid]; g2S[tid]=gf2[tid]; e2S[tid]=bef2[tid]; }
    for (int i = tid; i < 384; i += 256) wf3S[i] = Wf3[i];
    if (tid < 96)  fwS[tid]=g_fw[p0*3 + tid];
    if (tid < 3)   bf3S[tid]=bf3[tid];
    idxS[tid] = g_idx[p0*8 + tid];
    if (tid < 64) { g2v[tid]=g2[tid]; be2v[tid]=be2[tid]; }
    __syncthreads();

    {
        int pt = tid & 31, grp = tid >> 5, d0 = grp * 8;
        int p = p0 + pt;
        int bbase = p & ~(NN - 1);
        float4 a0 = *(const float4*)(g_A + p*64 + d0);
        float4 a1 = *(const float4*)(g_A + p*64 + d0 + 4);
        float4 gg0 = *(const float4*)(g2v + d0);
        float4 gg1 = *(const float4*)(g2v + d0 + 4);
        float4 ee0 = *(const float4*)(be2v + d0);
        float4 ee1 = *(const float4*)(be2v + d0 + 4);
        float m[8];
        #pragma unroll
        for (int u = 0; u < 8; u++) m[u] = -3.4e38f;
        #pragma unroll
        for (int k = 0; k < 8; k++) {
            int j = idxS[pt*8 + k];
            const float4* bp = (const float4*)(g_Bf + (bbase + j)*64 + d0);
            float4 v0 = bp[0], v1 = bp[1];
            m[0] = fmaxf(m[0], leaky(fmaf(a0.x + v0.x, gg0.x, ee0.x)));
            m[1] = fmaxf(m[1], leaky(fmaf(a0.y + v0.y, gg0.y, ee0.y)));
            m[2] = fmaxf(m[2], leaky(fmaf(a0.z + v0.z, gg0.z, ee0.z)));
            m[3] = fmaxf(m[3], leaky(fmaf(a0.w + v0.w, gg0.w, ee0.w)));
            m[4] = fmaxf(m[4], leaky(fmaf(a1.x + v1.x, gg1.x, ee1.x)));
            m[5] = fmaxf(m[5], leaky(fmaf(a1.y + v1.y, gg1.y, ee1.y)));
            m[6] = fmaxf(m[6], leaky(fmaf(a1.z + v1.z, gg1.z, ee1.z)));
            m[7] = fmaxf(m[7], leaky(fmaf(a1.w + v1.w, gg1.w, ee1.w)));
        }
        float fw0 = fwS[pt*3], fw1 = fwS[pt*3+1], fw2 = fwS[pt*3+2];
        #pragma unroll
        for (int dd = 0; dd < 8; dd++) {
            multiT[(d0+dd)*34 + pt]        = m[dd] * fw0;
            multiT[(64+d0+dd)*34 + pt]     = m[dd] * fw1;
            multiT[(128+d0+dd)*34 + pt]    = m[dd] * fw2;
        }
    }
    __syncthreads();

    // ---- layer 1: 192 -> 256 ----
    unsigned long long acc[4][4];
    #pragma unroll
    for (int i = 0; i < 4; i++)
        #pragma unroll
        for (int q = 0; q < 4; q++) acc[i][q] = 0ull;

    #pragma unroll
    for (int u = 0; u < 4; u++)
        *(float4*)(ws + (tid + u*256)*4) = *(const float4*)(Wf1 + (tid + u*256)*4);
    __syncthreads();

    for (int c = 0; c < 12; c++) {
        float4 pf[4];
        if (c < 11) {
            #pragma unroll
            for (int u = 0; u < 4; u++)
                pf[u] = *(const float4*)(Wf1 + (c+1)*4096 + (tid + u*256)*4);
        }
        const float* wb = ws + (c & 1) * 4096;
        #pragma unroll
        for (int kk = 0; kk < 16; kk++) {
            const unsigned long long* mrow =
                (const unsigned long long*)(multiT + (c*16 + kk)*34 + pbase);
            unsigned long long in0 = mrow[0], in1 = mrow[1], in2 = mrow[2], in3 = mrow[3];
            const float* wrow = wb + kk*256 + oh*128 + lane;
            #pragma unroll
            for (int i = 0; i < 4; i++) {
                unsigned long long wp = pack2(wrow[32*i]);
                acc[i][0] = ffma2(in0, wp, acc[i][0]);
                acc[i][1] = ffma2(in1, wp, acc[i][1]);
                acc[i][2] = ffma2(in2, wp, acc[i][2]);
                acc[i][3] = ffma2(in3, wp, acc[i][3]);
            }
        }
        if (c < 11) {
            float* wd = ws + ((c+1) & 1) * 4096;
            #pragma unroll
            for (int u = 0; u < 4; u++)
                *(float4*)(wd + (tid + u*256)*4) = pf[u];
        }
        __syncthreads();
    }
    #pragma unroll
    for (int i = 0; i < 4; i++) {
        int o = oh*128 + 32*i + lane;
        float bb = b1S[o], gg = g1S[o], ee = e1S[o];
        #pragma unroll
        for (int q = 0; q < 4; q++) {
            float2 v = *(float2*)&acc[i][q];
            float2 hv;
            hv.x = leaky(fmaf(v.x + bb, gg, ee));
            hv.y = leaky(fmaf(v.y + bb, gg, ee));
            *(float2*)(h1T + o*34 + pbase + 2*q) = hv;
        }
    }
    __syncthreads();

    // ---- layer 2: 256 -> 128 ----
    unsigned long long a2[2][4];
    #pragma unroll
    for (int i = 0; i < 2; i++)
        #pragma unroll
        for (int q = 0; q < 4; q++) a2[i][q] = 0ull;

    #pragma unroll
    for (int u = 0; u < 2; u++)
        *(float4*)(ws + (tid + u*256)*4) = *(const float4*)(Wf2 + (tid + u*256)*4);
    __syncthreads();

    for (int c = 0; c < 16; c++) {
        float4 pf[2];
        if (c < 15) {
            #pragma unroll
            for (int u = 0; u < 2; u++)
                pf[u] = *(const float4*)(Wf2 + (c+1)*2048 + (tid + u*256)*4);
        }
        const float* wb = ws + (c & 1) * 2048;
        #pragma unroll
        for (int kk = 0; kk < 16; kk++) {
            const unsigned long long* hrow =
                (const unsigned long long*)(h1T + (c*16 + kk)*34 + pbase);
            unsigned long long in0 = hrow[0], in1 = hrow[1], in2 = hrow[2], in3 = hrow[3];
            const float* wrow = wb + kk*128 + oh*64 + lane;
            #pragma unroll
            for (int i = 0; i < 2; i++) {
                unsigned long long wp = pack2(wrow[32*i]);
                a2[i][0] = ffma2(in0, wp, a2[i][0]);
                a2[i][1] = ffma2(in1, wp, a2[i][1]);
                a2[i][2] = ffma2(in2, wp, a2[i][2]);
                a2[i][3] = ffma2(in3, wp, a2[i][3]);
            }
        }
        if (c < 15) {
            float* wd = ws + ((c+1) & 1) * 2048;
            #pragma unroll
            for (int u = 0; u < 2; u++)
                *(float4*)(wd + (tid + u*256)*4) = pf[u];
        }
        __syncthreads();
    }
    #pragma unroll
    for (int i = 0; i < 2; i++) {
        int o = oh*64 + 32*i + lane;
        float bb = b2S[o], gg = g2S[o], ee = e2S[o];
        #pragma unroll
        for (int q = 0; q < 4; q++) {
            float2 v = *(float2*)&a2[i][q];
            float2 hv;
            hv.x = leaky(fmaf(v.x + bb, gg, ee));
            hv.y = leaky(fmaf(v.y + bb, gg, ee));
            *(float2*)(h2T + o*34 + pbase + 2*q) = hv;
        }
    }
    __syncthreads();

    // ---- layer 3: 128 -> 3 + residual ----
    if (tid < 96) {
        int pt = tid / 3, cc = tid - pt*3;
        float s0 = 0.f, s1 = 0.f;
        #pragma unroll 8
        for (int k = 0; k < 128; k += 2) {
            s0 = fmaf(h2T[k*34 + pt],     wf3S[k*3 + cc],     s0);
            s1 = fmaf(h2T[(k+1)*34 + pt], wf3S[(k+1)*3 + cc], s1);
        }
        int gp = p0 + pt;
        out[gp*3 + cc] = fmaf(0.1f, (s0 + s1) + bf3S[cc], x[gp*3 + cc]);
    }
}

// ---------------------------------------------------------------------------
extern "C" void kernel_launch(void* const* d_in, const int* in_sizes, int n_in,
                              void* d_out, int out_size)
{
    const float* x    = (const float*)d_in[0];
    const float* W1   = (const float*)d_in[1];
    const float* b1   = (const float*)d_in[2];
    const float* g1   = (const float*)d_in[3];
    const float* be1  = (const float*)d_in[4];
    const float* W2   = (const float*)d_in[5];
    const float* b2   = (const float*)d_in[6];
    const float* g2   = (const float*)d_in[7];
    const float* be2  = (const float*)d_in[8];
    const float* Ws1  = (const float*)d_in[9];
    const float* bs1  = (const float*)d_in[10];
    const float* Ws2  = (const float*)d_in[11];
    const float* bs2  = (const float*)d_in[12];
    const float* Wf1  = (const float*)d_in[13];
    const float* bf1  = (const float*)d_in[14];
    const float* gf1  = (const float*)d_in[15];
    const float* bef1 = (const float*)d_in[16];
    const float* Wf2  = (const float*)d_in[17];
    const float* bf2  = (const float*)d_in[18];
    const float* gf2  = (const float*)d_in[19];
    const float* bef2 = (const float*)d_in[20];
    const float* Wf3  = (const float*)d_in[21];
    const float* bf3  = (const float*)d_in[22];
    float* out = (float*)d_out;

    const int SM1 = 25988 * 4;   // k_prep shared bytes (~104KB)
    const int SM4 = 25444 * 4;   // k_fuse shared bytes (~101.8KB)

    cudaFuncSetAttribute(k_prep, cudaFuncAttributeMaxDynamicSharedMemorySize, SM1);
    cudaFuncSetAttribute(k_fuse, cudaFuncAttributeMaxDynamicSharedMemorySize, SM4);

    k_prep<<<128, 256, SM1>>>(x, W1, b1, g1, be1, W2, b2, Ws1, bs1, Ws2, bs2);
    k_knn<<<dim3(32, 8, NZONE), 256>>>(x);
    k_merge<<<PTS/256, 256>>>();
    k_fuse<<<PTS/PTB, 256, SM4>>>(x, g2, be2, Wf1, bf1, gf1, bef1,
                                  Wf2, bf2, gf2, bef2, Wf3, bf3, out);
}

// round 10
// speedup vs baseline: 2.2107x; 2.2107x over previous
#include <cuda_runtime.h>
#include <math.h>

// Problem constants
#define BB 8
#define NN 2048
#define PTS (BB*NN)      // 16384
#define DD 64
#define KK 8
#define LV 3
#define H1 256
#define H2 128
#define PTB 32           // points per k_fuse block
#define PTK 16           // points per k_knn block

// Scratch (device globals; no allocation allowed)
__device__ float g_A  [PTS*DD];
__device__ float g_Bf [PTS*DD];
__device__ float g_fw [PTS*LV];
__device__ int   g_idx[PTS*KK];

__device__ __forceinline__ float leaky(float v){ return v > 0.f ? v : 0.2f*v; }

__device__ __forceinline__ unsigned long long ffma2(unsigned long long a, unsigned long long b, unsigned long long c){
    asm("fma.rn.f32x2 %0, %1, %2, %0;" : "+l"(c) : "l"(a), "l"(b));
    return c;
}
__device__ __forceinline__ unsigned long long pack2(float w){
    unsigned long long r;
    asm("mov.b64 %0, {%1, %1};" : "=l"(r) : "f"(w));
    return r;
}

// ---------------------------------------------------------------------------
// K1: per-point prep (proven R4 config: 64 pts/block, grid 256).
// ---------------------------------------------------------------------------
__global__ void k_prep(const float* __restrict__ x,
                       const float* __restrict__ W1, const float* __restrict__ b1,
                       const float* __restrict__ g1, const float* __restrict__ be1,
                       const float* __restrict__ W2, const float* __restrict__ b2,
                       const float* __restrict__ Ws1, const float* __restrict__ bs1,
                       const float* __restrict__ Ws2, const float* __restrict__ bs2)
{
    extern __shared__ float sm[];
    float* W2s   = sm;               // 8192
    float* featS = W2s + 8192;       // 64*65 = 4160
    float* ssS   = featS + 4160;     // 4096
    float* W1s   = ssS + 4096;       // 192
    float* Ws1s  = W1s + 192;        // 192
    float* Ws2s  = Ws1s + 192;       // 192
    float* b1v   = Ws2s + 192;       // 64
    float* g1v   = b1v + 64;
    float* be1v  = g1v + 64;
    float* b2v   = be1v + 64;
    float* bs1v  = b2v + 64;
    float* bs2v  = bs1v + 64;        // 4
    float* xs    = bs2v + 4;         // 192

    const int tid = threadIdx.x;
    const int p0  = blockIdx.x * 64;

    for (int i = tid; i < 8192; i += 256) W2s[i] = W2[i];
    for (int i = tid; i < 192; i += 256) { W1s[i] = W1[i]; Ws1s[i] = Ws1[i]; Ws2s[i] = Ws2[i]; xs[i] = x[p0*3 + i]; }
    if (tid < 64) { b1v[tid]=b1[tid]; g1v[tid]=g1[tid]; be1v[tid]=be1[tid]; b2v[tid]=b2[tid]; bs1v[tid]=bs1[tid]; }
    if (tid < 3)  bs2v[tid] = bs2[tid];
    __syncthreads();

    for (int i = tid; i < 4096; i += 256) {
        int pt = i >> 6, d = i & 63;
        float x0 = xs[pt*3], x1 = xs[pt*3+1], x2 = xs[pt*3+2];
        float f = fmaf(x2, W1s[128+d], fmaf(x1, W1s[64+d], fmaf(x0, W1s[d], b1v[d])));
        f = fmaf(f, g1v[d], be1v[d]);
        featS[pt*65 + d] = leaky(f);
        float s = fmaf(x2, Ws1s[128+d], fmaf(x1, Ws1s[64+d], fmaf(x0, Ws1s[d], bs1v[d])));
        ssS[pt*64 + d] = s > 0.f ? s : 0.f;
    }
    __syncthreads();

    if (tid < 192) {
        int pt = tid / 3, l = tid - pt*3;
        float s = bs2v[l];
        #pragma unroll 8
        for (int d = 0; d < 64; d++) s = fmaf(ssS[pt*64 + d], Ws2s[d*3 + l], s);
        g_fw[(p0+pt)*3 + l] = 1.f / (1.f + expf(-s));
    }

    // A / Bf : thread = (pt, group of 16 output dims); FFMA2-paired outputs
    {
        int pt  = tid & 63;
        int grp = tid >> 6;
        unsigned long long accA[8], accB[8];
        #pragma unroll
        for (int u = 0; u < 8; u++) {
            accA[u] = *(const unsigned long long*)(b2v + grp*16 + 2*u);
            accB[u] = 0ull;
        }
        #pragma unroll 4
        for (int d = 0; d < 64; d++) {
            unsigned long long fv2 = pack2(featS[pt*65 + d]);
            const unsigned long long* wa = (const unsigned long long*)(W2s + d*64       + grp*16);
            const unsigned long long* wb = (const unsigned long long*)(W2s + (64+d)*64  + grp*16);
            #pragma unroll
            for (int u = 0; u < 8; u++) {
                accA[u] = ffma2(wa[u], fv2, accA[u]);
                accB[u] = ffma2(wb[u], fv2, accB[u]);
            }
        }
        float2* pA = (float2*)(g_A  + (p0+pt)*64 + grp*16);
        float2* pB = (float2*)(g_Bf + (p0+pt)*64 + grp*16);
        #pragma unroll
        for (int u = 0; u < 8; u++) {
            pA[u] = *(float2*)&accA[u];
            pB[u] = *(float2*)&accB[u];
        }
    }
}

// ---------------------------------------------------------------------------
// K2: KNN. grid (128, 8): 16 points/block, 8 j-splits x 16 pts = 128 threads.
// ~1024 blocks -> ~7 blocks/SM (occupancy + balance). 256 j per thread.
// e_j = xj.n - 2*(xi.xj): rank-equivalent to d2 for fixed i; single-insert
// top-8 (strict less, ascending j -> stable); in-block lexicographic merge.
// ---------------------------------------------------------------------------
__global__ void k_knn(const float* __restrict__ x)
{
    __shared__ __align__(16) float4 xsh[NN];   // 32 KB
    __shared__ float md[PTK*65];
    __shared__ int   mi[PTK*65];

    const int tid = threadIdx.x;               // 128
    const int b   = blockIdx.y;
    const int pl0 = blockIdx.x * PTK;

    for (int j = tid; j < NN; j += 128) {
        const float* xp = x + (b*NN + j)*3;
        float x0 = xp[0], x1 = xp[1], x2 = xp[2];
        xsh[j] = make_float4(x0, x1, x2, fmaf(x2, x2, fmaf(x1, x1, x0*x0)));
    }
    __syncthreads();

    const int pt = tid & (PTK-1), split = tid >> 4;
    float4 xi = xsh[pl0 + pt];
    const float ax = -2.f*xi.x, ay = -2.f*xi.y, az = -2.f*xi.z;

    float bd[8]; int bi[8];
    #pragma unroll
    for (int s = 0; s < 8; s++) { bd[s] = 3.4e38f; bi[s] = 0x7fffffff; }

    const int j0 = split * 256;
    #pragma unroll 4
    for (int j = j0; j < j0 + 256; j++) {
        float4 xj = xsh[j];
        float e = fmaf(xj.x, ax, fmaf(xj.y, ay, fmaf(xj.z, az, xj.w)));
        if (e < bd[7]) {
            int pos = 7;
            #pragma unroll
            for (int s = 6; s >= 0; s--) if (e < bd[s]) pos = s;
            #pragma unroll
            for (int s = 7; s >= 1; s--) if (s > pos) { bd[s] = bd[s-1]; bi[s] = bi[s-1]; }
            bd[pos] = e; bi[pos] = j;
        }
    }

    #pragma unroll
    for (int s = 0; s < 8; s++) { md[pt*65 + split*8 + s] = bd[s]; mi[pt*65 + split*8 + s] = bi[s]; }
    __syncthreads();

    if (tid < PTK) {
        float fd[8]; int fi[8];
        #pragma unroll
        for (int s = 0; s < 8; s++) { fd[s] = 3.4e38f; fi[s] = 0x7fffffff; }
        for (int c = 0; c < 64; c++) {
            float cd = md[tid*65 + c]; int ci = mi[tid*65 + c];
            bool ins = (cd < fd[7]) || (cd == fd[7] && ci < fi[7]);
            if (ins) {
                int pos = 7;
                #pragma unroll
                for (int s = 6; s >= 0; s--) if (cd < fd[s] || (cd == fd[s] && ci < fi[s])) pos = s;
                #pragma unroll
                for (int s = 7; s >= 1; s--) if (s > pos) { fd[s] = fd[s-1]; fi[s] = fi[s-1]; }
                fd[pos] = cd; fi[pos] = ci;
            }
        }
        int gp = b*NN + pl0 + tid;
        #pragma unroll
        for (int s = 0; s < 8; s++) g_idx[gp*8 + s] = fi[s];
    }
}

// ---------------------------------------------------------------------------
// K3 (fused): gather+edge-max+fw -> multiT (smem), then fusion MLP.
// (proven R4/R9 code, 87.6 us measured)
// ---------------------------------------------------------------------------
__global__ void __launch_bounds__(256, 2)
k_fuse(const float* __restrict__ x,
       const float* __restrict__ g2, const float* __restrict__ be2,
       const float* __restrict__ Wf1, const float* __restrict__ bf1,
       const float* __restrict__ gf1, const float* __restrict__ bef1,
       const float* __restrict__ Wf2, const float* __restrict__ bf2,
       const float* __restrict__ gf2, const float* __restrict__ bef2,
       const float* __restrict__ Wf3, const float* __restrict__ bf3,
       float* __restrict__ out)
{
    extern __shared__ float sm[];
    float* multiT = sm;                   // [192][34] ; h2T aliases [128][34]
    float* h2T    = sm;
    float* h1T    = sm + 6528;            // [256][34]
    float* ws     = sm + 15232;           // 2 x 4096
    float* b1S    = sm + 23424;
    float* g1S    = b1S + 256;
    float* e1S    = g1S + 256;
    float* b2S    = sm + 24192;
    float* g2S    = b2S + 128;
    float* e2S    = g2S + 128;
    float* wf3S   = sm + 24576;           // 384
    float* fwS    = sm + 24960;           // 96
    float* bf3S   = sm + 25056;           // 4
    int*   idxS   = (int*)(sm + 25060);   // 256
    float* g2v    = sm + 25316;           // 64
    float* be2v   = g2v + 64;             // 64 -> total 25444 floats

    const int tid  = threadIdx.x;
    const int lane = tid & 31;
    const int wrp  = tid >> 5;
    const int p0   = blockIdx.x * PTB;
    const int pg   = wrp & 3;
    const int oh   = wrp >> 2;
    const int pbase = pg * 8;

    { b1S[tid]=bf1[tid]; g1S[tid]=gf1[tid]; e1S[tid]=bef1[tid]; }
    if (tid < 128) { b2S[tid]=bf2[tid]; g2S[tid]=gf2[tid]; e2S[tid]=bef2[tid]; }
    for (int i = tid; i < 384; i += 256) wf3S[i] = Wf3[i];
    if (tid < 96)  fwS[tid]=g_fw[p0*3 + tid];
    if (tid < 3)   bf3S[tid]=bf3[tid];
    idxS[tid] = g_idx[p0*8 + tid];
    if (tid < 64) { g2v[tid]=g2[tid]; be2v[tid]=be2[tid]; }
    __syncthreads();

    {
        int pt = tid & 31, grp = tid >> 5, d0 = grp * 8;
        int p = p0 + pt;
        int bbase = p & ~(NN - 1);
        float4 a0 = *(const float4*)(g_A + p*64 + d0);
        float4 a1 = *(const float4*)(g_A + p*64 + d0 + 4);
        float4 gg0 = *(const float4*)(g2v + d0);
        float4 gg1 = *(const float4*)(g2v + d0 + 4);
        float4 ee0 = *(const float4*)(be2v + d0);
        float4 ee1 = *(const float4*)(be2v + d0 + 4);
        float m[8];
        #pragma unroll
        for (int u = 0; u < 8; u++) m[u] = -3.4e38f;
        #pragma unroll
        for (int k = 0; k < 8; k++) {
            int j = idxS[pt*8 + k];
            const float4* bp = (const float4*)(g_Bf + (bbase + j)*64 + d0);
            float4 v0 = bp[0], v1 = bp[1];
            m[0] = fmaxf(m[0], leaky(fmaf(a0.x + v0.x, gg0.x, ee0.x)));
            m[1] = fmaxf(m[1], leaky(fmaf(a0.y + v0.y, gg0.y, ee0.y)));
            m[2] = fmaxf(m[2], leaky(fmaf(a0.z + v0.z, gg0.z, ee0.z)));
            m[3] = fmaxf(m[3], leaky(fmaf(a0.w + v0.w, gg0.w, ee0.w)));
            m[4] = fmaxf(m[4], leaky(fmaf(a1.x + v1.x, gg1.x, ee1.x)));
            m[5] = fmaxf(m[5], leaky(fmaf(a1.y + v1.y, gg1.y, ee1.y)));
            m[6] = fmaxf(m[6], leaky(fmaf(a1.z + v1.z, gg1.z, ee1.z)));
            m[7] = fmaxf(m[7], leaky(fmaf(a1.w + v1.w, gg1.w, ee1.w)));
        }
        float fw0 = fwS[pt*3], fw1 = fwS[pt*3+1], fw2 = fwS[pt*3+2];
        #pragma unroll
        for (int dd = 0; dd < 8; dd++) {
            multiT[(d0+dd)*34 + pt]        = m[dd] * fw0;
            multiT[(64+d0+dd)*34 + pt]     = m[dd] * fw1;
            multiT[(128+d0+dd)*34 + pt]    = m[dd] * fw2;
        }
    }
    __syncthreads();

    // ---- layer 1: 192 -> 256 ----
    unsigned long long acc[4][4];
    #pragma unroll
    for (int i = 0; i < 4; i++)
        #pragma unroll
        for (int q = 0; q < 4; q++) acc[i][q] = 0ull;

    #pragma unroll
    for (int u = 0; u < 4; u++)
        *(float4*)(ws + (tid + u*256)*4) = *(const float4*)(Wf1 + (tid + u*256)*4);
    __syncthreads();

    for (int c = 0; c < 12; c++) {
        float4 pf[4];
        if (c < 11) {
            #pragma unroll
            for (int u = 0; u < 4; u++)
                pf[u] = *(const float4*)(Wf1 + (c+1)*4096 + (tid + u*256)*4);
        }
        const float* wb = ws + (c & 1) * 4096;
        #pragma unroll
        for (int kk = 0; kk < 16; kk++) {
            const unsigned long long* mrow =
                (const unsigned long long*)(multiT + (c*16 + kk)*34 + pbase);
            unsigned long long in0 = mrow[0], in1 = mrow[1], in2 = mrow[2], in3 = mrow[3];
            const float* wrow = wb + kk*256 + oh*128 + lane;
            #pragma unroll
            for (int i = 0; i < 4; i++) {
                unsigned long long wp = pack2(wrow[32*i]);
                acc[i][0] = ffma2(in0, wp, acc[i][0]);
                acc[i][1] = ffma2(in1, wp, acc[i][1]);
                acc[i][2] = ffma2(in2, wp, acc[i][2]);
                acc[i][3] = ffma2(in3, wp, acc[i][3]);
            }
        }
        if (c < 11) {
            float* wd = ws + ((c+1) & 1) * 4096;
            #pragma unroll
            for (int u = 0; u < 4; u++)
                *(float4*)(wd + (tid + u*256)*4) = pf[u];
        }
        __syncthreads();
    }
    #pragma unroll
    for (int i = 0; i < 4; i++) {
        int o = oh*128 + 32*i + lane;
        float bb = b1S[o], gg = g1S[o], ee = e1S[o];
        #pragma unroll
        for (int q = 0; q < 4; q++) {
            float2 v = *(float2*)&acc[i][q];
            float2 hv;
            hv.x = leaky(fmaf(v.x + bb, gg, ee));
            hv.y = leaky(fmaf(v.y + bb, gg, ee));
            *(float2*)(h1T + o*34 + pbase + 2*q) = hv;
        }
    }
    __syncthreads();

    // ---- layer 2: 256 -> 128 ----
    unsigned long long a2[2][4];
    #pragma unroll
    for (int i = 0; i < 2; i++)
        #pragma unroll
        for (int q = 0; q < 4; q++) a2[i][q] = 0ull;

    #pragma unroll
    for (int u = 0; u < 2; u++)
        *(float4*)(ws + (tid + u*256)*4) = *(const float4*)(Wf2 + (tid + u*256)*4);
    __syncthreads();

    for (int c = 0; c < 16; c++) {
        float4 pf[2];
        if (c < 15) {
            #pragma unroll
            for (int u = 0; u < 2; u++)
                pf[u] = *(const float4*)(Wf2 + (c+1)*2048 + (tid + u*256)*4);
        }
        const float* wb = ws + (c & 1) * 2048;
        #pragma unroll
        for (int kk = 0; kk < 16; kk++) {
            const unsigned long long* hrow =
                (const unsigned long long*)(h1T + (c*16 + kk)*34 + pbase);
            unsigned long long in0 = hrow[0], in1 = hrow[1], in2 = hrow[2], in3 = hrow[3];
            const float* wrow = wb + kk*128 + oh*64 + lane;
            #pragma unroll
            for (int i = 0; i < 2; i++) {
                unsigned long long wp = pack2(wrow[32*i]);
                a2[i][0] = ffma2(in0, wp, a2[i][0]);
                a2[i][1] = ffma2(in1, wp, a2[i][1]);
                a2[i][2] = ffma2(in2, wp, a2[i][2]);
                a2[i][3] = ffma2(in3, wp, a2[i][3]);
            }
        }
        if (c < 15) {
            float* wd = ws + ((c+1) & 1) * 2048;
            #pragma unroll
            for (int u = 0; u < 2; u++)
                *(float4*)(wd + (tid + u*256)*4) = pf[u];
        }
        __syncthreads();
    }
    #pragma unroll
    for (int i = 0; i < 2; i++) {
        int o = oh*64 + 32*i + lane;
        float bb = b2S[o], gg = g2S[o], ee = e2S[o];
        #pragma unroll
        for (int q = 0; q < 4; q++) {
            float2 v = *(float2*)&a2[i][q];
            float2 hv;
            hv.x = leaky(fmaf(v.x + bb, gg, ee));
            hv.y = leaky(fmaf(v.y + bb, gg, ee));
            *(float2*)(h2T + o*34 + pbase + 2*q) = hv;
        }
    }
    __syncthreads();

    // ---- layer 3: 128 -> 3 + residual ----
    if (tid < 96) {
        int pt = tid / 3, cc = tid - pt*3;
        float s0 = 0.f, s1 = 0.f;
        #pragma unroll 8
        for (int k = 0; k < 128; k += 2) {
            s0 = fmaf(h2T[k*34 + pt],     wf3S[k*3 + cc],     s0);
            s1 = fmaf(h2T[(k+1)*34 + pt], wf3S[(k+1)*3 + cc], s1);
        }
        int gp = p0 + pt;
        out[gp*3 + cc] = fmaf(0.1f, (s0 + s1) + bf3S[cc], x[gp*3 + cc]);
    }
}

// ---------------------------------------------------------------------------
extern "C" void kernel_launch(void* const* d_in, const int* in_sizes, int n_in,
                              void* d_out, int out_size)
{
    const float* x    = (const float*)d_in[0];
    const float* W1   = (const float*)d_in[1];
    const float* b1   = (const float*)d_in[2];
    const float* g1   = (const float*)d_in[3];
    const float* be1  = (const float*)d_in[4];
    const float* W2   = (const float*)d_in[5];
    const float* b2   = (const float*)d_in[6];
    const float* g2   = (const float*)d_in[7];
    const float* be2  = (const float*)d_in[8];
    const float* Ws1  = (const float*)d_in[9];
    const float* bs1  = (const float*)d_in[10];
    const float* Ws2  = (const float*)d_in[11];
    const float* bs2  = (const float*)d_in[12];
    const float* Wf1  = (const float*)d_in[13];
    const float* bf1  = (const float*)d_in[14];
    const float* gf1  = (const float*)d_in[15];
    const float* bef1 = (const float*)d_in[16];
    const float* Wf2  = (const float*)d_in[17];
    const float* bf2  = (const float*)d_in[18];
    const float* gf2  = (const float*)d_in[19];
    const float* bef2 = (const float*)d_in[20];
    const float* Wf3  = (const float*)d_in[21];
    const float* bf3  = (const float*)d_in[22];
    float* out = (float*)d_out;

    const int SM1 = 17540 * 4;   // k_prep shared bytes
    const int SM4 = 25444 * 4;   // k_fuse shared bytes (~101.8KB)

    cudaFuncSetAttribute(k_prep, cudaFuncAttributeMaxDynamicSharedMemorySize, SM1);
    cudaFuncSetAttribute(k_fuse, cudaFuncAttributeMaxDynamicSharedMemorySize, SM4);

    k_prep<<<256, 256, SM1>>>(x, W1, b1, g1, be1, W2, b2, Ws1, bs1, Ws2, bs2);
    k_knn<<<dim3(NN/PTK, BB), 128>>>(x);
    k_fuse<<<PTS/PTB, 256, SM4>>>(x, g2, be2, Wf1, bf1, gf1, bef1,
                                  Wf2, bf2, gf2, bef2, Wf3, bf3, out);
}

// round 11
// speedup vs baseline: 2.8719x; 1.2991x over previous
#include <cuda_runtime.h>
#include <math.h>

// Problem constants
#define BB 8
#define NN 2048
#define PTS (BB*NN)      // 16384
#define DD 64
#define KK 8
#define LV 3
#define H1 256
#define H2 128
#define PTB 32           // points per k_fuse block
#define KPT 32           // points per k_knn block

// Scratch (device globals; no allocation allowed)
__device__ float g_A  [PTS*DD];
__device__ float g_Bf [PTS*DD];
__device__ float g_fw [PTS*LV];
__device__ int   g_idx[PTS*KK];

__device__ __forceinline__ float leaky(float v){ return v > 0.f ? v : 0.2f*v; }

__device__ __forceinline__ unsigned long long ffma2(unsigned long long a, unsigned long long b, unsigned long long c){
    asm("fma.rn.f32x2 %0, %1, %2, %0;" : "+l"(c) : "l"(a), "l"(b));
    return c;
}
__device__ __forceinline__ unsigned long long pack2(float w){
    unsigned long long r;
    asm("mov.b64 %0, {%1, %1};" : "=l"(r) : "f"(w));
    return r;
}

// Branchless sorted-8 value insert: r[s] = min(bd[s], max(bd[s-1], e)).
#define VAL_INS8(B0,B1,B2,B3,B4,B5,B6,B7,E)            \
    {                                                  \
        float t0 = fminf(B0, E);                       \
        float t1 = fminf(B1, fmaxf(B0, E));            \
        float t2 = fminf(B2, fmaxf(B1, E));            \
        float t3 = fminf(B3, fmaxf(B2, E));            \
        float t4 = fminf(B4, fmaxf(B3, E));            \
        float t5 = fminf(B5, fmaxf(B4, E));            \
        float t6 = fminf(B6, fmaxf(B5, E));            \
        float t7 = fminf(B7, fmaxf(B6, E));            \
        B0=t0; B1=t1; B2=t2; B3=t3; B4=t4; B5=t5; B6=t6; B7=t7; \
    }

// ---------------------------------------------------------------------------
// K1: per-point prep (proven config: 64 pts/block, grid 256, 25.4us).
// ---------------------------------------------------------------------------
__global__ void k_prep(const float* __restrict__ x,
                       const float* __restrict__ W1, const float* __restrict__ b1,
                       const float* __restrict__ g1, const float* __restrict__ be1,
                       const float* __restrict__ W2, const float* __restrict__ b2,
                       const float* __restrict__ Ws1, const float* __restrict__ bs1,
                       const float* __restrict__ Ws2, const float* __restrict__ bs2)
{
    extern __shared__ float sm[];
    float* W2s   = sm;               // 8192
    float* featS = W2s + 8192;       // 64*65 = 4160
    float* ssS   = featS + 4160;     // 4096
    float* W1s   = ssS + 4096;       // 192
    float* Ws1s  = W1s + 192;        // 192
    float* Ws2s  = Ws1s + 192;       // 192
    float* b1v   = Ws2s + 192;       // 64
    float* g1v   = b1v + 64;
    float* be1v  = g1v + 64;
    float* b2v   = be1v + 64;
    float* bs1v  = b2v + 64;
    float* bs2v  = bs1v + 64;        // 4
    float* xs    = bs2v + 4;         // 192

    const int tid = threadIdx.x;
    const int p0  = blockIdx.x * 64;

    for (int i = tid; i < 8192; i += 256) W2s[i] = W2[i];
    for (int i = tid; i < 192; i += 256) { W1s[i] = W1[i]; Ws1s[i] = Ws1[i]; Ws2s[i] = Ws2[i]; xs[i] = x[p0*3 + i]; }
    if (tid < 64) { b1v[tid]=b1[tid]; g1v[tid]=g1[tid]; be1v[tid]=be1[tid]; b2v[tid]=b2[tid]; bs1v[tid]=bs1[tid]; }
    if (tid < 3)  bs2v[tid] = bs2[tid];
    __syncthreads();

    for (int i = tid; i < 4096; i += 256) {
        int pt = i >> 6, d = i & 63;
        float x0 = xs[pt*3], x1 = xs[pt*3+1], x2 = xs[pt*3+2];
        float f = fmaf(x2, W1s[128+d], fmaf(x1, W1s[64+d], fmaf(x0, W1s[d], b1v[d])));
        f = fmaf(f, g1v[d], be1v[d]);
        featS[pt*65 + d] = leaky(f);
        float s = fmaf(x2, Ws1s[128+d], fmaf(x1, Ws1s[64+d], fmaf(x0, Ws1s[d], bs1v[d])));
        ssS[pt*64 + d] = s > 0.f ? s : 0.f;
    }
    __syncthreads();

    if (tid < 192) {
        int pt = tid / 3, l = tid - pt*3;
        float s = bs2v[l];
        #pragma unroll 8
        for (int d = 0; d < 64; d++) s = fmaf(ssS[pt*64 + d], Ws2s[d*3 + l], s);
        g_fw[(p0+pt)*3 + l] = 1.f / (1.f + expf(-s));
    }

    // A / Bf : thread = (pt, group of 16 output dims); FFMA2-paired outputs
    {
        int pt  = tid & 63;
        int grp = tid >> 6;
        unsigned long long accA[8], accB[8];
        #pragma unroll
        for (int u = 0; u < 8; u++) {
            accA[u] = *(const unsigned long long*)(b2v + grp*16 + 2*u);
            accB[u] = 0ull;
        }
        #pragma unroll 4
        for (int d = 0; d < 64; d++) {
            unsigned long long fv2 = pack2(featS[pt*65 + d]);
            const unsigned long long* wa = (const unsigned long long*)(W2s + d*64       + grp*16);
            const unsigned long long* wb = (const unsigned long long*)(W2s + (64+d)*64  + grp*16);
            #pragma unroll
            for (int u = 0; u < 8; u++) {
                accA[u] = ffma2(wa[u], fv2, accA[u]);
                accB[u] = ffma2(wb[u], fv2, accB[u]);
            }
        }
        float2* pA = (float2*)(g_A  + (p0+pt)*64 + grp*16);
        float2* pB = (float2*)(g_Bf + (p0+pt)*64 + grp*16);
        #pragma unroll
        for (int u = 0; u < 8; u++) {
            pA[u] = *(float2*)&accA[u];
            pB[u] = *(float2*)&accB[u];
        }
    }
}

// ---------------------------------------------------------------------------
// K2: KNN, two-phase. grid (64, 8): 32 pts/block, 4 splits x 32 = 128 threads.
// Pass1: branchless value-only sorted-8 (16 FMNMX, no spills).
// tau-merge: exact 8th-smallest value per point.
// Pass2: rescan, collect all e <= tau (identical fmaf expr -> identical e).
// Final: lexicographic (e, idx) top-8 from <= ~12 candidates. Exact set.
// ---------------------------------------------------------------------------
__global__ void k_knn(const float* __restrict__ x)
{
    extern __shared__ float ksm[];
    float4* xsh  = (float4*)ksm;             // [2048] = 8192 floats (32KB)
    float*  md   = ksm + 8192;               // [32*33] = 1056
    float*  tauS = ksm + 9248;               // 32
    float*  cbE  = ksm + 9280;               // 128*12 = 1536
    int*    cbJ  = (int*)(ksm + 10816);      // 1536
    int*    cntS = (int*)(ksm + 12352);      // 128  -> total 12480 floats (49.9KB)

    const int tid = threadIdx.x;             // 128
    const int b   = blockIdx.y;
    const int pl0 = blockIdx.x * KPT;

    for (int j = tid; j < NN; j += 128) {
        const float* xp = x + (b*NN + j)*3;
        float x0 = xp[0], x1 = xp[1], x2 = xp[2];
        xsh[j] = make_float4(x0, x1, x2, fmaf(x2, x2, fmaf(x1, x1, x0*x0)));
    }
    __syncthreads();

    const int pt = tid & 31, split = tid >> 5;
    float4 xi = xsh[pl0 + pt];
    const float ax = -2.f*xi.x, ay = -2.f*xi.y, az = -2.f*xi.z;
    const int j0 = split * 512;

    // ---- pass 1: values only ----
    float b0=3.4e38f,b1=3.4e38f,b2=3.4e38f,b3=3.4e38f,
          b4=3.4e38f,b5=3.4e38f,b6=3.4e38f,b7=3.4e38f;
    #pragma unroll 4
    for (int j = j0; j < j0 + 512; j++) {
        float4 xj = xsh[j];
        float e = fmaf(xj.x, ax, fmaf(xj.y, ay, fmaf(xj.z, az, xj.w)));
        if (e < b7) VAL_INS8(b0,b1,b2,b3,b4,b5,b6,b7,e);
    }
    {
        float* mrow = md + pt*33 + split*8;
        mrow[0]=b0; mrow[1]=b1; mrow[2]=b2; mrow[3]=b3;
        mrow[4]=b4; mrow[5]=b5; mrow[6]=b6; mrow[7]=b7;
    }
    __syncthreads();

    // ---- tau merge: 8th-smallest value of union of 4 partial lists ----
    if (tid < 32) {
        float s0=3.4e38f,s1=3.4e38f,s2=3.4e38f,s3=3.4e38f,
              s4=3.4e38f,s5=3.4e38f,s6=3.4e38f,s7=3.4e38f;
        #pragma unroll
        for (int c = 0; c < 32; c++) {
            float e = md[tid*33 + c];
            if (e < s7) VAL_INS8(s0,s1,s2,s3,s4,s5,s6,s7,e);
        }
        tauS[tid] = s7;
    }
    __syncthreads();

    // ---- pass 2: collect candidates e <= tau ----
    const float tau = tauS[pt];
    int cnt = 0;
    #pragma unroll 4
    for (int j = j0; j < j0 + 512; j++) {
        float4 xj = xsh[j];
        float e = fmaf(xj.x, ax, fmaf(xj.y, ay, fmaf(xj.z, az, xj.w)));
        if (e <= tau) {
            if (cnt < 12) { cbE[tid*12 + cnt] = e; cbJ[tid*12 + cnt] = j; }
            cnt++;
        }
    }
    cntS[tid] = cnt < 12 ? cnt : 12;
    __syncthreads();

    // ---- final: exact lexicographic (e, idx) top-8 ----
    if (tid < 32) {
        int gp = b*NN + pl0 + tid;
        #pragma unroll
        for (int r = 0; r < 8; r++) {
            float be = 3.4e38f; int bj = 0x7fffffff; int loc = 0;
            for (int s = 0; s < 4; s++) {
                int t = tid + 32*s;
                int c = cntS[t];
                for (int k = 0; k < c; k++) {
                    float e = cbE[t*12 + k]; int jj = cbJ[t*12 + k];
                    if (e < be || (e == be && jj < bj)) { be = e; bj = jj; loc = t*12 + k; }
                }
            }
            cbE[loc] = 3.4e38f;
            g_idx[gp*8 + r] = bj;
        }
    }
}

// ---------------------------------------------------------------------------
// K3 (fused): gather+edge-max+fw -> multiT (smem), then fusion MLP.
// (proven code, ~88us measured)
// ---------------------------------------------------------------------------
__global__ void __launch_bounds__(256, 2)
k_fuse(const float* __restrict__ x,
       const float* __restrict__ g2, const float* __restrict__ be2,
       const float* __restrict__ Wf1, const float* __restrict__ bf1,
       const float* __restrict__ gf1, const float* __restrict__ bef1,
       const float* __restrict__ Wf2, const float* __restrict__ bf2,
       const float* __restrict__ gf2, const float* __restrict__ bef2,
       const float* __restrict__ Wf3, const float* __restrict__ bf3,
       float* __restrict__ out)
{
    extern __shared__ float sm[];
    float* multiT = sm;                   // [192][34] ; h2T aliases [128][34]
    float* h2T    = sm;
    float* h1T    = sm + 6528;            // [256][34]
    float* ws     = sm + 15232;           // 2 x 4096
    float* b1S    = sm + 23424;
    float* g1S    = b1S + 256;
    float* e1S    = g1S + 256;
    float* b2S    = sm + 24192;
    float* g2S    = b2S + 128;
    float* e2S    = g2S + 128;
    float* wf3S   = sm + 24576;           // 384
    float* fwS    = sm + 24960;           // 96
    float* bf3S   = sm + 25056;           // 4
    int*   idxS   = (int*)(sm + 25060);   // 256
    float* g2v    = sm + 25316;           // 64
    float* be2v   = g2v + 64;             // 64 -> total 25444 floats

    const int tid  = threadIdx.x;
    const int lane = tid & 31;
    const int wrp  = tid >> 5;
    const int p0   = blockIdx.x * PTB;
    const int pg   = wrp & 3;
    const int oh   = wrp >> 2;
    const int pbase = pg * 8;

    { b1S[tid]=bf1[tid]; g1S[tid]=gf1[tid]; e1S[tid]=bef1[tid]; }
    if (tid < 128) { b2S[tid]=bf2[tid]; g2S[tid]=gf2[tid]; e2S[tid]=bef2[tid]; }
    for (int i = tid; i < 384; i += 256) wf3S[i] = Wf3[i];
    if (tid < 96)  fwS[tid]=g_fw[p0*3 + tid];
    if (tid < 3)   bf3S[tid]=bf3[tid];
    idxS[tid] = g_idx[p0*8 + tid];
    if (tid < 64) { g2v[tid]=g2[tid]; be2v[tid]=be2[tid]; }
    __syncthreads();

    {
        int pt = tid & 31, grp = tid >> 5, d0 = grp * 8;
        int p = p0 + pt;
        int bbase = p & ~(NN - 1);
        float4 a0 = *(const float4*)(g_A + p*64 + d0);
        float4 a1 = *(const float4*)(g_A + p*64 + d0 + 4);
        float4 gg0 = *(const float4*)(g2v + d0);
        float4 gg1 = *(const float4*)(g2v + d0 + 4);
        float4 ee0 = *(const float4*)(be2v + d0);
        float4 ee1 = *(const float4*)(be2v + d0 + 4);
        float m[8];
        #pragma unroll
        for (int u = 0; u < 8; u++) m[u] = -3.4e38f;
        #pragma unroll
        for (int k = 0; k < 8; k++) {
            int j = idxS[pt*8 + k];
            const float4* bp = (const float4*)(g_Bf + (bbase + j)*64 + d0);
            float4 v0 = bp[0], v1 = bp[1];
            m[0] = fmaxf(m[0], leaky(fmaf(a0.x + v0.x, gg0.x, ee0.x)));
            m[1] = fmaxf(m[1], leaky(fmaf(a0.y + v0.y, gg0.y, ee0.y)));
            m[2] = fmaxf(m[2], leaky(fmaf(a0.z + v0.z, gg0.z, ee0.z)));
            m[3] = fmaxf(m[3], leaky(fmaf(a0.w + v0.w, gg0.w, ee0.w)));
            m[4] = fmaxf(m[4], leaky(fmaf(a1.x + v1.x, gg1.x, ee1.x)));
            m[5] = fmaxf(m[5], leaky(fmaf(a1.y + v1.y, gg1.y, ee1.y)));
            m[6] = fmaxf(m[6], leaky(fmaf(a1.z + v1.z, gg1.z, ee1.z)));
            m[7] = fmaxf(m[7], leaky(fmaf(a1.w + v1.w, gg1.w, ee1.w)));
        }
        float fw0 = fwS[pt*3], fw1 = fwS[pt*3+1], fw2 = fwS[pt*3+2];
        #pragma unroll
        for (int dd = 0; dd < 8; dd++) {
            multiT[(d0+dd)*34 + pt]        = m[dd] * fw0;
            multiT[(64+d0+dd)*34 + pt]     = m[dd] * fw1;
            multiT[(128+d0+dd)*34 + pt]    = m[dd] * fw2;
        }
    }
    __syncthreads();

    // ---- layer 1: 192 -> 256 ----
    unsigned long long acc[4][4];
    #pragma unroll
    for (int i = 0; i < 4; i++)
        #pragma unroll
        for (int q = 0; q < 4; q++) acc[i][q] = 0ull;

    #pragma unroll
    for (int u = 0; u < 4; u++)
        *(float4*)(ws + (tid + u*256)*4) = *(const float4*)(Wf1 + (tid + u*256)*4);
    __syncthreads();

    for (int c = 0; c < 12; c++) {
        float4 pf[4];
        if (c < 11) {
            #pragma unroll
            for (int u = 0; u < 4; u++)
                pf[u] = *(const float4*)(Wf1 + (c+1)*4096 + (tid + u*256)*4);
        }
        const float* wb = ws + (c & 1) * 4096;
        #pragma unroll
        for (int kk = 0; kk < 16; kk++) {
            const unsigned long long* mrow =
                (const unsigned long long*)(multiT + (c*16 + kk)*34 + pbase);
            unsigned long long in0 = mrow[0], in1 = mrow[1], in2 = mrow[2], in3 = mrow[3];
            const float* wrow = wb + kk*256 + oh*128 + lane;
            #pragma unroll
            for (int i = 0; i < 4; i++) {
                unsigned long long wp = pack2(wrow[32*i]);
                acc[i][0] = ffma2(in0, wp, acc[i][0]);
                acc[i][1] = ffma2(in1, wp, acc[i][1]);
                acc[i][2] = ffma2(in2, wp, acc[i][2]);
                acc[i][3] = ffma2(in3, wp, acc[i][3]);
            }
        }
        if (c < 11) {
            float* wd = ws + ((c+1) & 1) * 4096;
            #pragma unroll
            for (int u = 0; u < 4; u++)
                *(float4*)(wd + (tid + u*256)*4) = pf[u];
        }
        __syncthreads();
    }
    #pragma unroll
    for (int i = 0; i < 4; i++) {
        int o = oh*128 + 32*i + lane;
        float bb = b1S[o], gg = g1S[o], ee = e1S[o];
        #pragma unroll
        for (int q = 0; q < 4; q++) {
            float2 v = *(float2*)&acc[i][q];
            float2 hv;
            hv.x = leaky(fmaf(v.x + bb, gg, ee));
            hv.y = leaky(fmaf(v.y + bb, gg, ee));
            *(float2*)(h1T + o*34 + pbase + 2*q) = hv;
        }
    }
    __syncthreads();

    // ---- layer 2: 256 -> 128 ----
    unsigned long long a2[2][4];
    #pragma unroll
    for (int i = 0; i < 2; i++)
        #pragma unroll
        for (int q = 0; q < 4; q++) a2[i][q] = 0ull;

    #pragma unroll
    for (int u = 0; u < 2; u++)
        *(float4*)(ws + (tid + u*256)*4) = *(const float4*)(Wf2 + (tid + u*256)*4);
    __syncthreads();

    for (int c = 0; c < 16; c++) {
        float4 pf[2];
        if (c < 15) {
            #pragma unroll
            for (int u = 0; u < 2; u++)
                pf[u] = *(const float4*)(Wf2 + (c+1)*2048 + (tid + u*256)*4);
        }
        const float* wb = ws + (c & 1) * 2048;
        #pragma unroll
        for (int kk = 0; kk < 16; kk++) {
            const unsigned long long* hrow =
                (const unsigned long long*)(h1T + (c*16 + kk)*34 + pbase);
            unsigned long long in0 = hrow[0], in1 = hrow[1], in2 = hrow[2], in3 = hrow[3];
            const float* wrow = wb + kk*128 + oh*64 + lane;
            #pragma unroll
            for (int i = 0; i < 2; i++) {
                unsigned long long wp = pack2(wrow[32*i]);
                a2[i][0] = ffma2(in0, wp, a2[i][0]);
                a2[i][1] = ffma2(in1, wp, a2[i][1]);
                a2[i][2] = ffma2(in2, wp, a2[i][2]);
                a2[i][3] = ffma2(in3, wp, a2[i][3]);
            }
        }
        if (c < 15) {
            float* wd = ws + ((c+1) & 1) * 2048;
            #pragma unroll
            for (int u = 0; u < 2; u++)
                *(float4*)(wd + (tid + u*256)*4) = pf[u];
        }
        __syncthreads();
    }
    #pragma unroll
    for (int i = 0; i < 2; i++) {
        int o = oh*64 + 32*i + lane;
        float bb = b2S[o], gg = g2S[o], ee = e2S[o];
        #pragma unroll
        for (int q = 0; q < 4; q++) {
            float2 v = *(float2*)&a2[i][q];
            float2 hv;
            hv.x = leaky(fmaf(v.x + bb, gg, ee));
            hv.y = leaky(fmaf(v.y + bb, gg, ee));
            *(float2*)(h2T + o*34 + pbase + 2*q) = hv;
        }
    }
    __syncthreads();

    // ---- layer 3: 128 -> 3 + residual ----
    if (tid < 96) {
        int pt = tid / 3, cc = tid - pt*3;
        float s0 = 0.f, s1 = 0.f;
        #pragma unroll 8
        for (int k = 0; k < 128; k += 2) {
            s0 = fmaf(h2T[k*34 + pt],     wf3S[k*3 + cc],     s0);
            s1 = fmaf(h2T[(k+1)*34 + pt], wf3S[(k+1)*3 + cc], s1);
        }
        int gp = p0 + pt;
        out[gp*3 + cc] = fmaf(0.1f, (s0 + s1) + bf3S[cc], x[gp*3 + cc]);
    }
}

// ---------------------------------------------------------------------------
extern "C" void kernel_launch(void* const* d_in, const int* in_sizes, int n_in,
                              void* d_out, int out_size)
{
    const float* x    = (const float*)d_in[0];
    const float* W1   = (const float*)d_in[1];
    const float* b1   = (const float*)d_in[2];
    const float* g1   = (const float*)d_in[3];
    const float* be1  = (const float*)d_in[4];
    const float* W2   = (const float*)d_in[5];
    const float* b2   = (const float*)d_in[6];
    const float* g2   = (const float*)d_in[7];
    const float* be2  = (const float*)d_in[8];
    const float* Ws1  = (const float*)d_in[9];
    const float* bs1  = (const float*)d_in[10];
    const float* Ws2  = (const float*)d_in[11];
    const float* bs2  = (const float*)d_in[12];
    const float* Wf1  = (const float*)d_in[13];
    const float* bf1  = (const float*)d_in[14];
    const float* gf1  = (const float*)d_in[15];
    const float* bef1 = (const float*)d_in[16];
    const float* Wf2  = (const float*)d_in[17];
    const float* bf2  = (const float*)d_in[18];
    const float* gf2  = (const float*)d_in[19];
    const float* bef2 = (const float*)d_in[20];
    const float* Wf3  = (const float*)d_in[21];
    const float* bf3  = (const float*)d_in[22];
    float* out = (float*)d_out;

    const int SM1 = 17540 * 4;   // k_prep shared bytes
    const int SM2 = 12480 * 4;   // k_knn shared bytes (49.9KB)
    const int SM4 = 25444 * 4;   // k_fuse shared bytes (~101.8KB)

    cudaFuncSetAttribute(k_prep, cudaFuncAttributeMaxDynamicSharedMemorySize, SM1);
    cudaFuncSetAttribute(k_knn,  cudaFuncAttributeMaxDynamicSharedMemorySize, SM2);
    cudaFuncSetAttribute(k_fuse, cudaFuncAttributeMaxDynamicSharedMemorySize, SM4);

    k_prep<<<256, 256, SM1>>>(x, W1, b1, g1, be1, W2, b2, Ws1, bs1, Ws2, bs2);
    k_knn<<<dim3(NN/KPT, BB), 128, SM2>>>(x);
    k_fuse<<<PTS/PTB, 256, SM4>>>(x, g2, be2, Wf1, bf1, gf1, bef1,
                                  Wf2, bf2, gf2, bef2, Wf3, bf3, out);
}

// round 13
// speedup vs baseline: 3.4665x; 1.2070x over previous
#include <cuda_runtime.h>
#include <math.h>

// Problem constants
#define BB 8
#define NN 2048
#define PTS (BB*NN)      // 16384
#define DD 64
#define KK 8
#define LV 3
#define H1 256
#define H2 128
#define PTB 32           // points per k_fuse block
#define KPT 32           // points per k_knn block

// Scratch (device globals; no allocation allowed)
__device__ float g_A  [PTS*DD];
__device__ float g_Bf [PTS*DD];
__device__ float g_fw [PTS*LV];
__device__ int   g_idx[PTS*KK];

__device__ __forceinline__ float leaky(float v){ return v > 0.f ? v : 0.2f*v; }

__device__ __forceinline__ unsigned long long ffma2(unsigned long long a, unsigned long long b, unsigned long long c){
    asm("fma.rn.f32x2 %0, %1, %2, %0;" : "+l"(c) : "l"(a), "l"(b));
    return c;
}
__device__ __forceinline__ unsigned long long pack2(float w){
    unsigned long long r;
    asm("mov.b64 %0, {%1, %1};" : "=l"(r) : "f"(w));
    return r;
}

// Branchless sorted-8 insert: r[s] = min(b[s], max(b[s-1], e)).
#define VAL_INS8(B0,B1,B2,B3,B4,B5,B6,B7,E)            \
    {                                                  \
        float t0 = fminf(B0, E);                       \
        float t1 = fminf(B1, fmaxf(B0, E));            \
        float t2 = fminf(B2, fmaxf(B1, E));            \
        float t3 = fminf(B3, fmaxf(B2, E));            \
        float t4 = fminf(B4, fmaxf(B3, E));            \
        float t5 = fminf(B5, fmaxf(B4, E));            \
        float t6 = fminf(B6, fmaxf(B5, E));            \
        float t7 = fminf(B7, fmaxf(B6, E));            \
        B0=t0; B1=t1; B2=t2; B3=t3; B4=t4; B5=t5; B6=t6; B7=t7; \
    }

// ---------------------------------------------------------------------------
// K1: per-point prep (proven config: 64 pts/block, grid 256, 25.4us).
// ---------------------------------------------------------------------------
__global__ void k_prep(const float* __restrict__ x,
                       const float* __restrict__ W1, const float* __restrict__ b1,
                       const float* __restrict__ g1, const float* __restrict__ be1,
                       const float* __restrict__ W2, const float* __restrict__ b2,
                       const float* __restrict__ Ws1, const float* __restrict__ bs1,
                       const float* __restrict__ Ws2, const float* __restrict__ bs2)
{
    extern __shared__ float sm[];
    float* W2s   = sm;               // 8192
    float* featS = W2s + 8192;       // 64*65 = 4160
    float* ssS   = featS + 4160;     // 4096
    float* W1s   = ssS + 4096;       // 192
    float* Ws1s  = W1s + 192;        // 192
    float* Ws2s  = Ws1s + 192;       // 192
    float* b1v   = Ws2s + 192;       // 64
    float* g1v   = b1v + 64;
    float* be1v  = g1v + 64;
    float* b2v   = be1v + 64;
    float* bs1v  = b2v + 64;
    float* bs2v  = bs1v + 64;        // 4
    float* xs    = bs2v + 4;         // 192

    const int tid = threadIdx.x;
    const int p0  = blockIdx.x * 64;

    for (int i = tid; i < 8192; i += 256) W2s[i] = W2[i];
    for (int i = tid; i < 192; i += 256) { W1s[i] = W1[i]; Ws1s[i] = Ws1[i]; Ws2s[i] = Ws2[i]; xs[i] = x[p0*3 + i]; }
    if (tid < 64) { b1v[tid]=b1[tid]; g1v[tid]=g1[tid]; be1v[tid]=be1[tid]; b2v[tid]=b2[tid]; bs1v[tid]=bs1[tid]; }
    if (tid < 3)  bs2v[tid] = bs2[tid];
    __syncthreads();

    for (int i = tid; i < 4096; i += 256) {
        int pt = i >> 6, d = i & 63;
        float x0 = xs[pt*3], x1 = xs[pt*3+1], x2 = xs[pt*3+2];
        float f = fmaf(x2, W1s[128+d], fmaf(x1, W1s[64+d], fmaf(x0, W1s[d], b1v[d])));
        f = fmaf(f, g1v[d], be1v[d]);
        featS[pt*65 + d] = leaky(f);
        float s = fmaf(x2, Ws1s[128+d], fmaf(x1, Ws1s[64+d], fmaf(x0, Ws1s[d], bs1v[d])));
        ssS[pt*64 + d] = s > 0.f ? s : 0.f;
    }
    __syncthreads();

    if (tid < 192) {
        int pt = tid / 3, l = tid - pt*3;
        float s = bs2v[l];
        #pragma unroll 8
        for (int d = 0; d < 64; d++) s = fmaf(ssS[pt*64 + d], Ws2s[d*3 + l], s);
        g_fw[(p0+pt)*3 + l] = 1.f / (1.f + expf(-s));
    }

    // A / Bf : thread = (pt, group of 16 output dims); FFMA2-paired outputs
    {
        int pt  = tid & 63;
        int grp = tid >> 6;
        unsigned long long accA[8], accB[8];
        #pragma unroll
        for (int u = 0; u < 8; u++) {
            accA[u] = *(const unsigned long long*)(b2v + grp*16 + 2*u);
            accB[u] = 0ull;
        }
        #pragma unroll 4
        for (int d = 0; d < 64; d++) {
            unsigned long long fv2 = pack2(featS[pt*65 + d]);
            const unsigned long long* wa = (const unsigned long long*)(W2s + d*64       + grp*16);
            const unsigned long long* wb = (const unsigned long long*)(W2s + (64+d)*64  + grp*16);
            #pragma unroll
            for (int u = 0; u < 8; u++) {
                accA[u] = ffma2(wa[u], fv2, accA[u]);
                accB[u] = ffma2(wb[u], fv2, accB[u]);
            }
        }
        float2* pA = (float2*)(g_A  + (p0+pt)*64 + grp*16);
        float2* pB = (float2*)(g_Bf + (p0+pt)*64 + grp*16);
        #pragma unroll
        for (int u = 0; u < 8; u++) {
            pA[u] = *(float2*)&accA[u];
            pB[u] = *(float2*)&accB[u];
        }
    }
}

// ---------------------------------------------------------------------------
// K2: KNN, single-pass keyed. grid (64, 8): 32 pts/block, 4 splits x 512 j.
// key = (bits(d2) & ~0x7FF) | j  -- non-negative floats order like their bits,
// so the branchless FMNMX sorted-8 carries (d2-rank, j-tiebreak) together.
// Final: merge 4 sorted-8 key lists per point, decode j from low 11 bits.
// ---------------------------------------------------------------------------
__global__ void k_knn(const float* __restrict__ x)
{
    __shared__ __align__(16) float4 xsh[NN];   // 32 KB
    __shared__ float mk[KPT*33];               // 32 pts x (4 splits x 8), padded

    const int tid = threadIdx.x;               // 128
    const int b   = blockIdx.y;
    const int pl0 = blockIdx.x * KPT;

    for (int j = tid; j < NN; j += 128) {
        const float* xp = x + (b*NN + j)*3;
        float x0 = xp[0], x1 = xp[1], x2 = xp[2];
        xsh[j] = make_float4(x0, x1, x2, fmaf(x2, x2, fmaf(x1, x1, x0*x0)));
    }
    __syncthreads();

    const int pt = tid & 31, split = tid >> 5;
    float4 xi = xsh[pl0 + pt];
    const float ax = -2.f*xi.x, ay = -2.f*xi.y, az = -2.f*xi.z;
    const float bias = xi.w;
    const int j0 = split * 512;

    float b0=3.4e38f,b1=3.4e38f,b2=3.4e38f,b3=3.4e38f,
          b4=3.4e38f,b5=3.4e38f,b6=3.4e38f,b7=3.4e38f;
    #pragma unroll 4
    for (int j = j0; j < j0 + 512; j++) {
        float4 xj = xsh[j];
        float d2 = fmaf(xj.x, ax, fmaf(xj.y, ay, fmaf(xj.z, az, xj.w))) + bias;
        unsigned kb = (__float_as_uint(d2) & 0xFFFFF800u) | (unsigned)j;
        float key = __uint_as_float(kb);
        if (key < b7) VAL_INS8(b0,b1,b2,b3,b4,b5,b6,b7,key);
    }
    {
        float* mrow = mk + pt*33 + split*8;
        mrow[0]=b0; mrow[1]=b1; mrow[2]=b2; mrow[3]=b3;
        mrow[4]=b4; mrow[5]=b5; mrow[6]=b6; mrow[7]=b7;
    }
    __syncthreads();

    if (tid < KPT) {
        float s0=3.4e38f,s1=3.4e38f,s2=3.4e38f,s3=3.4e38f,
              s4=3.4e38f,s5=3.4e38f,s6=3.4e38f,s7=3.4e38f;
        #pragma unroll
        for (int c = 0; c < 32; c++) {
            float v = mk[tid*33 + c];
            if (v < s7) VAL_INS8(s0,s1,s2,s3,s4,s5,s6,s7,v);
        }
        int gp = b*NN + pl0 + tid;
        g_idx[gp*8 + 0] = (int)(__float_as_uint(s0) & 0x7FFu);
        g_idx[gp*8 + 1] = (int)(__float_as_uint(s1) & 0x7FFu);
        g_idx[gp*8 + 2] = (int)(__float_as_uint(s2) & 0x7FFu);
        g_idx[gp*8 + 3] = (int)(__float_as_uint(s3) & 0x7FFu);
        g_idx[gp*8 + 4] = (int)(__float_as_uint(s4) & 0x7FFu);
        g_idx[gp*8 + 5] = (int)(__float_as_uint(s5) & 0x7FFu);
        g_idx[gp*8 + 6] = (int)(__float_as_uint(s6) & 0x7FFu);
        g_idx[gp*8 + 7] = (int)(__float_as_uint(s7) & 0x7FFu);
    }
}

// ---------------------------------------------------------------------------
// K3 (fused): gather+edge-max+fw -> multiT (smem), then fusion MLP.
// (proven code, ~88us measured)
// ---------------------------------------------------------------------------
__global__ void __launch_bounds__(256, 2)
k_fuse(const float* __restrict__ x,
       const float* __restrict__ g2, const float* __restrict__ be2,
       const float* __restrict__ Wf1, const float* __restrict__ bf1,
       const float* __restrict__ gf1, const float* __restrict__ bef1,
       const float* __restrict__ Wf2, const float* __restrict__ bf2,
       const float* __restrict__ gf2, const float* __restrict__ bef2,
       const float* __restrict__ Wf3, const float* __restrict__ bf3,
       float* __restrict__ out)
{
    extern __shared__ float sm[];
    float* multiT = sm;                   // [192][34] ; h2T aliases [128][34]
    float* h2T    = sm;
    float* h1T    = sm + 6528;            // [256][34]
    float* ws     = sm + 15232;           // 2 x 4096
    float* b1S    = sm + 23424;
    float* g1S    = b1S + 256;
    float* e1S    = g1S + 256;
    float* b2S    = sm + 24192;
    float* g2S    = b2S + 128;
    float* e2S    = g2S + 128;
    float* wf3S   = sm + 24576;           // 384
    float* fwS    = sm + 24960;           // 96
    float* bf3S   = sm + 25056;           // 4
    int*   idxS   = (int*)(sm + 25060);   // 256
    float* g2v    = sm + 25316;           // 64
    float* be2v   = g2v + 64;             // 64 -> total 25444 floats

    const int tid  = threadIdx.x;
    const int lane = tid & 31;
    const int wrp  = tid >> 5;
    const int p0   = blockIdx.x * PTB;
    const int pg   = wrp & 3;
    const int oh   = wrp >> 2;
    const int pbase = pg * 8;

    { b1S[tid]=bf1[tid]; g1S[tid]=gf1[tid]; e1S[tid]=bef1[tid]; }
    if (tid < 128) { b2S[tid]=bf2[tid]; g2S[tid]=gf2[tid]; e2S[tid]=bef2[tid]; }
    for (int i = tid; i < 384; i += 256) wf3S[i] = Wf3[i];
    if (tid < 96)  fwS[tid]=g_fw[p0*3 + tid];
    if (tid < 3)   bf3S[tid]=bf3[tid];
    idxS[tid] = g_idx[p0*8 + tid];
    if (tid < 64) { g2v[tid]=g2[tid]; be2v[tid]=be2[tid]; }
    __syncthreads();

    {
        int pt = tid & 31, grp = tid >> 5, d0 = grp * 8;
        int p = p0 + pt;
        int bbase = p & ~(NN - 1);
        float4 a0 = *(const float4*)(g_A + p*64 + d0);
        float4 a1 = *(const float4*)(g_A + p*64 + d0 + 4);
        float4 gg0 = *(const float4*)(g2v + d0);
        float4 gg1 = *(const float4*)(g2v + d0 + 4);
        float4 ee0 = *(const float4*)(be2v + d0);
        float4 ee1 = *(const float4*)(be2v + d0 + 4);
        float m[8];
        #pragma unroll
        for (int u = 0; u < 8; u++) m[u] = -3.4e38f;
        #pragma unroll
        for (int k = 0; k < 8; k++) {
            int j = idxS[pt*8 + k];
            const float4* bp = (const float4*)(g_Bf + (bbase + j)*64 + d0);
            float4 v0 = bp[0], v1 = bp[1];
            m[0] = fmaxf(m[0], leaky(fmaf(a0.x + v0.x, gg0.x, ee0.x)));
            m[1] = fmaxf(m[1], leaky(fmaf(a0.y + v0.y, gg0.y, ee0.y)));
            m[2] = fmaxf(m[2], leaky(fmaf(a0.z + v0.z, gg0.z, ee0.z)));
            m[3] = fmaxf(m[3], leaky(fmaf(a0.w + v0.w, gg0.w, ee0.w)));
            m[4] = fmaxf(m[4], leaky(fmaf(a1.x + v1.x, gg1.x, ee1.x)));
            m[5] = fmaxf(m[5], leaky(fmaf(a1.y + v1.y, gg1.y, ee1.y)));
            m[6] = fmaxf(m[6], leaky(fmaf(a1.z + v1.z, gg1.z, ee1.z)));
            m[7] = fmaxf(m[7], leaky(fmaf(a1.w + v1.w, gg1.w, ee1.w)));
        }
        float fw0 = fwS[pt*3], fw1 = fwS[pt*3+1], fw2 = fwS[pt*3+2];
        #pragma unroll
        for (int dd = 0; dd < 8; dd++) {
            multiT[(d0+dd)*34 + pt]        = m[dd] * fw0;
            multiT[(64+d0+dd)*34 + pt]     = m[dd] * fw1;
            multiT[(128+d0+dd)*34 + pt]    = m[dd] * fw2;
        }
    }
    __syncthreads();

    // ---- layer 1: 192 -> 256 ----
    unsigned long long acc[4][4];
    #pragma unroll
    for (int i = 0; i < 4; i++)
        #pragma unroll
        for (int q = 0; q < 4; q++) acc[i][q] = 0ull;

    #pragma unroll
    for (int u = 0; u < 4; u++)
        *(float4*)(ws + (tid + u*256)*4) = *(const float4*)(Wf1 + (tid + u*256)*4);
    __syncthreads();

    for (int c = 0; c < 12; c++) {
        float4 pf[4];
        if (c < 11) {
            #pragma unroll
            for (int u = 0; u < 4; u++)
                pf[u] = *(const float4*)(Wf1 + (c+1)*4096 + (tid + u*256)*4);
        }
        const float* wb = ws + (c & 1) * 4096;
        #pragma unroll
        for (int kk = 0; kk < 16; kk++) {
            const unsigned long long* mrow =
                (const unsigned long long*)(multiT + (c*16 + kk)*34 + pbase);
            unsigned long long in0 = mrow[0], in1 = mrow[1], in2 = mrow[2], in3 = mrow[3];
            const float* wrow = wb + kk*256 + oh*128 + lane;
            #pragma unroll
            for (int i = 0; i < 4; i++) {
                unsigned long long wp = pack2(wrow[32*i]);
                acc[i][0] = ffma2(in0, wp, acc[i][0]);
                acc[i][1] = ffma2(in1, wp, acc[i][1]);
                acc[i][2] = ffma2(in2, wp, acc[i][2]);
                acc[i][3] = ffma2(in3, wp, acc[i][3]);
            }
        }
        if (c < 11) {
            float* wd = ws + ((c+1) & 1) * 4096;
            #pragma unroll
            for (int u = 0; u < 4; u++)
                *(float4*)(wd + (tid + u*256)*4) = pf[u];
        }
        __syncthreads();
    }
    #pragma unroll
    for (int i = 0; i < 4; i++) {
        int o = oh*128 + 32*i + lane;
        float bb = b1S[o], gg = g1S[o], ee = e1S[o];
        #pragma unroll
        for (int q = 0; q < 4; q++) {
            float2 v = *(float2*)&acc[i][q];
            float2 hv;
            hv.x = leaky(fmaf(v.x + bb, gg, ee));
            hv.y = leaky(fmaf(v.y + bb, gg, ee));
            *(float2*)(h1T + o*34 + pbase + 2*q) = hv;
        }
    }
    __syncthreads();

    // ---- layer 2: 256 -> 128 ----
    unsigned long long a2[2][4];
    #pragma unroll
    for (int i = 0; i < 2; i++)
        #pragma unroll
        for (int q = 0; q < 4; q++) a2[i][q] = 0ull;

    #pragma unroll
    for (int u = 0; u < 2; u++)
        *(float4*)(ws + (tid + u*256)*4) = *(const float4*)(Wf2 + (tid + u*256)*4);
    __syncthreads();

    for (int c = 0; c < 16; c++) {
        float4 pf[2];
        if (c < 15) {
            #pragma unroll
            for (int u = 0; u < 2; u++)
                pf[u] = *(const float4*)(Wf2 + (c+1)*2048 + (tid + u*256)*4);
        }
        const float* wb = ws + (c & 1) * 2048;
        #pragma unroll
        for (int kk = 0; kk < 16; kk++) {
            const unsigned long long* hrow =
                (const unsigned long long*)(h1T + (c*16 + kk)*34 + pbase);
            unsigned long long in0 = hrow[0], in1 = hrow[1], in2 = hrow[2], in3 = hrow[3];
            const float* wrow = wb + kk*128 + oh*64 + lane;
            #pragma unroll
            for (int i = 0; i < 2; i++) {
                unsigned long long wp = pack2(wrow[32*i]);
                a2[i][0] = ffma2(in0, wp, a2[i][0]);
                a2[i][1] = ffma2(in1, wp, a2[i][1]);
                a2[i][2] = ffma2(in2, wp, a2[i][2]);
                a2[i][3] = ffma2(in3, wp, a2[i][3]);
            }
        }
        if (c < 15) {
            float* wd = ws + ((c+1) & 1) * 2048;
            #pragma unroll
            for (int u = 0; u < 2; u++)
                *(float4*)(wd + (tid + u*256)*4) = pf[u];
        }
        __syncthreads();
    }
    #pragma unroll
    for (int i = 0; i < 2; i++) {
        int o = oh*64 + 32*i + lane;
        float bb = b2S[o], gg = g2S[o], ee = e2S[o];
        #pragma unroll
        for (int q = 0; q < 4; q++) {
            float2 v = *(float2*)&a2[i][q];
            float2 hv;
            hv.x = leaky(fmaf(v.x + bb, gg, ee));
            hv.y = leaky(fmaf(v.y + bb, gg, ee));
            *(float2*)(h2T + o*34 + pbase + 2*q) = hv;
        }
    }
    __syncthreads();

    // ---- layer 3: 128 -> 3 + residual ----
    if (tid < 96) {
        int pt = tid / 3, cc = tid - pt*3;
        float s0 = 0.f, s1 = 0.f;
        #pragma unroll 8
        for (int k = 0; k < 128; k += 2) {
            s0 = fmaf(h2T[k*34 + pt],     wf3S[k*3 + cc],     s0);
            s1 = fmaf(h2T[(k+1)*34 + pt], wf3S[(k+1)*3 + cc], s1);
        }
        int gp = p0 + pt;
        out[gp*3 + cc] = fmaf(0.1f, (s0 + s1) + bf3S[cc], x[gp*3 + cc]);
    }
}

// ---------------------------------------------------------------------------
extern "C" void kernel_launch(void* const* d_in, const int* in_sizes, int n_in,
                              void* d_out, int out_size)
{
    const float* x    = (const float*)d_in[0];
    const float* W1   = (const float*)d_in[1];
    const float* b1   = (const float*)d_in[2];
    const float* g1   = (const float*)d_in[3];
    const float* be1  = (const float*)d_in[4];
    const float* W2   = (const float*)d_in[5];
    const float* b2   = (const float*)d_in[6];
    const float* g2   = (const float*)d_in[7];
    const float* be2  = (const float*)d_in[8];
    const float* Ws1  = (const float*)d_in[9];
    const float* bs1  = (const float*)d_in[10];
    const float* Ws2  = (const float*)d_in[11];
    const float* bs2  = (const float*)d_in[12];
    const float* Wf1  = (const float*)d_in[13];
    const float* bf1  = (const float*)d_in[14];
    const float* gf1  = (const float*)d_in[15];
    const float* bef1 = (const float*)d_in[16];
    const float* Wf2  = (const float*)d_in[17];
    const float* bf2  = (const float*)d_in[18];
    const float* gf2  = (const float*)d_in[19];
    const float* bef2 = (const float*)d_in[20];
    const float* Wf3  = (const float*)d_in[21];
    const float* bf3  = (const float*)d_in[22];
    float* out = (float*)d_out;

    const int SM1 = 17540 * 4;   // k_prep shared bytes
    const int SM4 = 25444 * 4;   // k_fuse shared bytes (~101.8KB)

    cudaFuncSetAttribute(k_prep, cudaFuncAttributeMaxDynamicSharedMemorySize, SM1);
    cudaFuncSetAttribute(k_fuse, cudaFuncAttributeMaxDynamicSharedMemorySize, SM4);

    k_prep<<<256, 256, SM1>>>(x, W1, b1, g1, be1, W2, b2, Ws1, bs1, Ws2, bs2);
    k_knn<<<dim3(NN/KPT, BB), 128>>>(x);
    k_fuse<<<PTS/PTB, 256, SM4>>>(x, g2, be2, Wf1, bf1, gf1, bef1,
                                  Wf2, bf2, gf2, bef2, Wf3, bf3, out);
}

// round 14
// speedup vs baseline: 3.6755x; 1.0603x over previous
#include <cuda_runtime.h>
#include <math.h>

// Problem constants
#define BB 8
#define NN 2048
#define PTS (BB*NN)      // 16384
#define DD 64
#define KK 8
#define LV 3
#define H1 256
#define H2 128
#define PTB 32           // points per k_fuse block
#define KPT 32           // points per knn block
#define NKNNB (PTS/KPT)  // 512 knn blocks
#define NPREPB 256       // prep blocks (64 pts each)

// Scratch (device globals; no allocation allowed)
__device__ float g_A  [PTS*DD];
__device__ float g_Bf [PTS*DD];
__device__ float g_fw [PTS*LV];
__device__ int   g_idx[PTS*KK];

__device__ __forceinline__ float leaky(float v){ return v > 0.f ? v : 0.2f*v; }

__device__ __forceinline__ unsigned long long ffma2(unsigned long long a, unsigned long long b, unsigned long long c){
    asm("fma.rn.f32x2 %0, %1, %2, %0;" : "+l"(c) : "l"(a), "l"(b));
    return c;
}
__device__ __forceinline__ unsigned long long pack2(float w){
    unsigned long long r;
    asm("mov.b64 %0, {%1, %1};" : "=l"(r) : "f"(w));
    return r;
}

// Branchless sorted-8 insert: r[s] = min(b[s], max(b[s-1], e)).
#define VAL_INS8(B0,B1,B2,B3,B4,B5,B6,B7,E)            \
    {                                                  \
        float t0 = fminf(B0, E);                       \
        float t1 = fminf(B1, fmaxf(B0, E));            \
        float t2 = fminf(B2, fmaxf(B1, E));            \
        float t3 = fminf(B3, fmaxf(B2, E));            \
        float t4 = fminf(B4, fmaxf(B3, E));            \
        float t5 = fminf(B5, fmaxf(B4, E));            \
        float t6 = fminf(B6, fmaxf(B5, E));            \
        float t7 = fminf(B7, fmaxf(B6, E));            \
        B0=t0; B1=t1; B2=t2; B3=t3; B4=t4; B5=t5; B6=t6; B7=t7; \
    }

// ---------------------------------------------------------------------------
// K1 (merged): blocks [0, NKNNB) = KNN path; [NKNNB, NKNNB+NPREPB) = prep path.
// Heterogeneous grid overlaps the two independent stages on the chip.
// ---------------------------------------------------------------------------
__global__ void __launch_bounds__(256)
k_pk(const float* __restrict__ x,
     const float* __restrict__ W1, const float* __restrict__ b1,
     const float* __restrict__ g1, const float* __restrict__ be1,
     const float* __restrict__ W2, const float* __restrict__ b2,
     const float* __restrict__ Ws1, const float* __restrict__ bs1,
     const float* __restrict__ Ws2, const float* __restrict__ bs2)
{
    extern __shared__ float sm[];
    const int tid = threadIdx.x;

    if (blockIdx.x < NKNNB) {
        // =================== KNN path (256 threads, 32 pts, 8 splits) =======
        float4* xsh = (float4*)sm;             // [2048] float4 = 8192 floats
        float*  mk  = sm + 8192;               // [32][65] = 2080

        const int kb  = blockIdx.x;
        const int b   = kb >> 6;               // 64 blocks per batch
        const int pl0 = (kb & 63) * KPT;

        for (int j = tid; j < NN; j += 256) {
            const float* xp = x + (b*NN + j)*3;
            float x0 = xp[0], x1 = xp[1], x2 = xp[2];
            xsh[j] = make_float4(x0, x1, x2, fmaf(x2, x2, fmaf(x1, x1, x0*x0)));
        }
        __syncthreads();

        const int pt = tid & 31, split = tid >> 5;
        float4 xi = xsh[pl0 + pt];
        const float ax = -2.f*xi.x, ay = -2.f*xi.y, az = -2.f*xi.z;
        const float bias = xi.w;
        const int j0 = split * 256;

        float b0=3.4e38f,b1r=3.4e38f,b2r=3.4e38f,b3=3.4e38f,
              b4=3.4e38f,b5=3.4e38f,b6=3.4e38f,b7=3.4e38f;
        #pragma unroll 4
        for (int j = j0; j < j0 + 256; j++) {
            float4 xj = xsh[j];
            float d2 = fmaf(xj.x, ax, fmaf(xj.y, ay, fmaf(xj.z, az, xj.w))) + bias;
            unsigned kbits = (__float_as_uint(d2) & 0xFFFFF800u) | (unsigned)j;
            float key = __uint_as_float(kbits);
            if (key < b7) VAL_INS8(b0,b1r,b2r,b3,b4,b5,b6,b7,key);
        }
        {
            float* mrow = mk + pt*65 + split*8;
            mrow[0]=b0; mrow[1]=b1r; mrow[2]=b2r; mrow[3]=b3;
            mrow[4]=b4; mrow[5]=b5; mrow[6]=b6; mrow[7]=b7;
        }
        __syncthreads();

        if (tid < KPT) {
            float s0=3.4e38f,s1=3.4e38f,s2=3.4e38f,s3=3.4e38f,
                  s4=3.4e38f,s5=3.4e38f,s6=3.4e38f,s7=3.4e38f;
            #pragma unroll
            for (int c = 0; c < 64; c++) {
                float v = mk[tid*65 + c];
                if (v < s7) VAL_INS8(s0,s1,s2,s3,s4,s5,s6,s7,v);
            }
            int gp = b*NN + pl0 + tid;
            g_idx[gp*8 + 0] = (int)(__float_as_uint(s0) & 0x7FFu);
            g_idx[gp*8 + 1] = (int)(__float_as_uint(s1) & 0x7FFu);
            g_idx[gp*8 + 2] = (int)(__float_as_uint(s2) & 0x7FFu);
            g_idx[gp*8 + 3] = (int)(__float_as_uint(s3) & 0x7FFu);
            g_idx[gp*8 + 4] = (int)(__float_as_uint(s4) & 0x7FFu);
            g_idx[gp*8 + 5] = (int)(__float_as_uint(s5) & 0x7FFu);
            g_idx[gp*8 + 6] = (int)(__float_as_uint(s6) & 0x7FFu);
            g_idx[gp*8 + 7] = (int)(__float_as_uint(s7) & 0x7FFu);
        }
        return;
    }

    // ======================= prep path (verbatim) ===========================
    float* W2s   = sm;               // 8192
    float* featS = W2s + 8192;       // 64*65 = 4160
    float* ssS   = featS + 4160;     // 4096
    float* W1s   = ssS + 4096;       // 192
    float* Ws1s  = W1s + 192;        // 192
    float* Ws2s  = Ws1s + 192;       // 192
    float* b1v   = Ws2s + 192;       // 64
    float* g1v   = b1v + 64;
    float* be1v  = g1v + 64;
    float* b2v   = be1v + 64;
    float* bs1v  = b2v + 64;
    float* bs2v  = bs1v + 64;        // 4
    float* xs    = bs2v + 4;         // 192

    const int p0 = (blockIdx.x - NKNNB) * 64;

    for (int i = tid; i < 8192; i += 256) W2s[i] = W2[i];
    for (int i = tid; i < 192; i += 256) { W1s[i] = W1[i]; Ws1s[i] = Ws1[i]; Ws2s[i] = Ws2[i]; xs[i] = x[p0*3 + i]; }
    if (tid < 64) { b1v[tid]=b1[tid]; g1v[tid]=g1[tid]; be1v[tid]=be1[tid]; b2v[tid]=b2[tid]; bs1v[tid]=bs1[tid]; }
    if (tid < 3)  bs2v[tid] = bs2[tid];
    __syncthreads();

    for (int i = tid; i < 4096; i += 256) {
        int pt = i >> 6, d = i & 63;
        float x0 = xs[pt*3], x1 = xs[pt*3+1], x2 = xs[pt*3+2];
        float f = fmaf(x2, W1s[128+d], fmaf(x1, W1s[64+d], fmaf(x0, W1s[d], b1v[d])));
        f = fmaf(f, g1v[d], be1v[d]);
        featS[pt*65 + d] = leaky(f);
        float s = fmaf(x2, Ws1s[128+d], fmaf(x1, Ws1s[64+d], fmaf(x0, Ws1s[d], bs1v[d])));
        ssS[pt*64 + d] = s > 0.f ? s : 0.f;
    }
    __syncthreads();

    if (tid < 192) {
        int pt = tid / 3, l = tid - pt*3;
        float s = bs2v[l];
        #pragma unroll 8
        for (int d = 0; d < 64; d++) s = fmaf(ssS[pt*64 + d], Ws2s[d*3 + l], s);
        g_fw[(p0+pt)*3 + l] = 1.f / (1.f + expf(-s));
    }

    {
        int pt  = tid & 63;
        int grp = tid >> 6;
        unsigned long long accA[8], accB[8];
        #pragma unroll
        for (int u = 0; u < 8; u++) {
            accA[u] = *(const unsigned long long*)(b2v + grp*16 + 2*u);
            accB[u] = 0ull;
        }
        #pragma unroll 4
        for (int d = 0; d < 64; d++) {
            unsigned long long fv2 = pack2(featS[pt*65 + d]);
            const unsigned long long* wa = (const unsigned long long*)(W2s + d*64       + grp*16);
            const unsigned long long* wb = (const unsigned long long*)(W2s + (64+d)*64  + grp*16);
            #pragma unroll
            for (int u = 0; u < 8; u++) {
                accA[u] = ffma2(wa[u], fv2, accA[u]);
                accB[u] = ffma2(wb[u], fv2, accB[u]);
            }
        }
        float2* pA = (float2*)(g_A  + (p0+pt)*64 + grp*16);
        float2* pB = (float2*)(g_Bf + (p0+pt)*64 + grp*16);
        #pragma unroll
        for (int u = 0; u < 8; u++) {
            pA[u] = *(float2*)&accA[u];
            pB[u] = *(float2*)&accB[u];
        }
    }
}

// ---------------------------------------------------------------------------
// K3 (fused): gather+edge-max+fw -> multiT (smem), then fusion MLP.
// (proven code, ~88us measured)
// ---------------------------------------------------------------------------
__global__ void __launch_bounds__(256, 2)
k_fuse(const float* __restrict__ x,
       const float* __restrict__ g2, const float* __restrict__ be2,
       const float* __restrict__ Wf1, const float* __restrict__ bf1,
       const float* __restrict__ gf1, const float* __restrict__ bef1,
       const float* __restrict__ Wf2, const float* __restrict__ bf2,
       const float* __restrict__ gf2, const float* __restrict__ bef2,
       const float* __restrict__ Wf3, const float* __restrict__ bf3,
       float* __restrict__ out)
{
    extern __shared__ float sm[];
    float* multiT = sm;                   // [192][34] ; h2T aliases [128][34]
    float* h2T    = sm;
    float* h1T    = sm + 6528;            // [256][34]
    float* ws     = sm + 15232;           // 2 x 4096
    float* b1S    = sm + 23424;
    float* g1S    = b1S + 256;
    float* e1S    = g1S + 256;
    float* b2S    = sm + 24192;
    float* g2S    = b2S + 128;
    float* e2S    = g2S + 128;
    float* wf3S   = sm + 24576;           // 384
    float* fwS    = sm + 24960;           // 96
    float* bf3S   = sm + 25056;           // 4
    int*   idxS   = (int*)(sm + 25060);   // 256
    float* g2v    = sm + 25316;           // 64
    float* be2v   = g2v + 64;             // 64 -> total 25444 floats

    const int tid  = threadIdx.x;
    const int lane = tid & 31;
    const int wrp  = tid >> 5;
    const int p0   = blockIdx.x * PTB;
    const int pg   = wrp & 3;
    const int oh   = wrp >> 2;
    const int pbase = pg * 8;

    { b1S[tid]=bf1[tid]; g1S[tid]=gf1[tid]; e1S[tid]=bef1[tid]; }
    if (tid < 128) { b2S[tid]=bf2[tid]; g2S[tid]=gf2[tid]; e2S[tid]=bef2[tid]; }
    for (int i = tid; i < 384; i += 256) wf3S[i] = Wf3[i];
    if (tid < 96)  fwS[tid]=g_fw[p0*3 + tid];
    if (tid < 3)   bf3S[tid]=bf3[tid];
    idxS[tid] = g_idx[p0*8 + tid];
    if (tid < 64) { g2v[tid]=g2[tid]; be2v[tid]=be2[tid]; }
    __syncthreads();

    {
        int pt = tid & 31, grp = tid >> 5, d0 = grp * 8;
        int p = p0 + pt;
        int bbase = p & ~(NN - 1);
        float4 a0 = *(const float4*)(g_A + p*64 + d0);
        float4 a1 = *(const float4*)(g_A + p*64 + d0 + 4);
        float4 gg0 = *(const float4*)(g2v + d0);
        float4 gg1 = *(const float4*)(g2v + d0 + 4);
        float4 ee0 = *(const float4*)(be2v + d0);
        float4 ee1 = *(const float4*)(be2v + d0 + 4);
        float m[8];
        #pragma unroll
        for (int u = 0; u < 8; u++) m[u] = -3.4e38f;
        #pragma unroll
        for (int k = 0; k < 8; k++) {
            int j = idxS[pt*8 + k];
            const float4* bp = (const float4*)(g_Bf + (bbase + j)*64 + d0);
            float4 v0 = bp[0], v1 = bp[1];
            m[0] = fmaxf(m[0], leaky(fmaf(a0.x + v0.x, gg0.x, ee0.x)));
            m[1] = fmaxf(m[1], leaky(fmaf(a0.y + v0.y, gg0.y, ee0.y)));
            m[2] = fmaxf(m[2], leaky(fmaf(a0.z + v0.z, gg0.z, ee0.z)));
            m[3] = fmaxf(m[3], leaky(fmaf(a0.w + v0.w, gg0.w, ee0.w)));
            m[4] = fmaxf(m[4], leaky(fmaf(a1.x + v1.x, gg1.x, ee1.x)));
            m[5] = fmaxf(m[5], leaky(fmaf(a1.y + v1.y, gg1.y, ee1.y)));
            m[6] = fmaxf(m[6], leaky(fmaf(a1.z + v1.z, gg1.z, ee1.z)));
            m[7] = fmaxf(m[7], leaky(fmaf(a1.w + v1.w, gg1.w, ee1.w)));
        }
        float fw0 = fwS[pt*3], fw1 = fwS[pt*3+1], fw2 = fwS[pt*3+2];
        #pragma unroll
        for (int dd = 0; dd < 8; dd++) {
            multiT[(d0+dd)*34 + pt]        = m[dd] * fw0;
            multiT[(64+d0+dd)*34 + pt]     = m[dd] * fw1;
            multiT[(128+d0+dd)*34 + pt]    = m[dd] * fw2;
        }
    }
    __syncthreads();

    // ---- layer 1: 192 -> 256 ----
    unsigned long long acc[4][4];
    #pragma unroll
    for (int i = 0; i < 4; i++)
        #pragma unroll
        for (int q = 0; q < 4; q++) acc[i][q] = 0ull;

    #pragma unroll
    for (int u = 0; u < 4; u++)
        *(float4*)(ws + (tid + u*256)*4) = *(const float4*)(Wf1 + (tid + u*256)*4);
    __syncthreads();

    for (int c = 0; c < 12; c++) {
        float4 pf[4];
        if (c < 11) {
            #pragma unroll
            for (int u = 0; u < 4; u++)
                pf[u] = *(const float4*)(Wf1 + (c+1)*4096 + (tid + u*256)*4);
        }
        const float* wb = ws + (c & 1) * 4096;
        #pragma unroll
        for (int kk = 0; kk < 16; kk++) {
            const unsigned long long* mrow =
                (const unsigned long long*)(multiT + (c*16 + kk)*34 + pbase);
            unsigned long long in0 = mrow[0], in1 = mrow[1], in2 = mrow[2], in3 = mrow[3];
            const float* wrow = wb + kk*256 + oh*128 + lane;
            #pragma unroll
            for (int i = 0; i < 4; i++) {
                unsigned long long wp = pack2(wrow[32*i]);
                acc[i][0] = ffma2(in0, wp, acc[i][0]);
                acc[i][1] = ffma2(in1, wp, acc[i][1]);
                acc[i][2] = ffma2(in2, wp, acc[i][2]);
                acc[i][3] = ffma2(in3, wp, acc[i][3]);
            }
        }
        if (c < 11) {
            float* wd = ws + ((c+1) & 1) * 4096;
            #pragma unroll
            for (int u = 0; u < 4; u++)
                *(float4*)(wd + (tid + u*256)*4) = pf[u];
        }
        __syncthreads();
    }
    #pragma unroll
    for (int i = 0; i < 4; i++) {
        int o = oh*128 + 32*i + lane;
        float bb = b1S[o], gg = g1S[o], ee = e1S[o];
        #pragma unroll
        for (int q = 0; q < 4; q++) {
            float2 v = *(float2*)&acc[i][q];
            float2 hv;
            hv.x = leaky(fmaf(v.x + bb, gg, ee));
            hv.y = leaky(fmaf(v.y + bb, gg, ee));
            *(float2*)(h1T + o*34 + pbase + 2*q) = hv;
        }
    }
    __syncthreads();

    // ---- layer 2: 256 -> 128 ----
    unsigned long long a2[2][4];
    #pragma unroll
    for (int i = 0; i < 2; i++)
        #pragma unroll
        for (int q = 0; q < 4; q++) a2[i][q] = 0ull;

    #pragma unroll
    for (int u = 0; u < 2; u++)
        *(float4*)(ws + (tid + u*256)*4) = *(const float4*)(Wf2 + (tid + u*256)*4);
    __syncthreads();

    for (int c = 0; c < 16; c++) {
        float4 pf[2];
        if (c < 15) {
            #pragma unroll
            for (int u = 0; u < 2; u++)
                pf[u] = *(const float4*)(Wf2 + (c+1)*2048 + (tid + u*256)*4);
        }
        const float* wb = ws + (c & 1) * 2048;
        #pragma unroll
        for (int kk = 0; kk < 16; kk++) {
            const unsigned long long* hrow =
                (const unsigned long long*)(h1T + (c*16 + kk)*34 + pbase);
            unsigned long long in0 = hrow[0], in1 = hrow[1], in2 = hrow[2], in3 = hrow[3];
            const float* wrow = wb + kk*128 + oh*64 + lane;
            #pragma unroll
            for (int i = 0; i < 2; i++) {
                unsigned long long wp = pack2(wrow[32*i]);
                a2[i][0] = ffma2(in0, wp, a2[i][0]);
                a2[i][1] = ffma2(in1, wp, a2[i][1]);
                a2[i][2] = ffma2(in2, wp, a2[i][2]);
                a2[i][3] = ffma2(in3, wp, a2[i][3]);
            }
        }
        if (c < 15) {
            float* wd = ws + ((c+1) & 1) * 2048;
            #pragma unroll
            for (int u = 0; u < 2; u++)
                *(float4*)(wd + (tid + u*256)*4) = pf[u];
        }
        __syncthreads();
    }
    #pragma unroll
    for (int i = 0; i < 2; i++) {
        int o = oh*64 + 32*i + lane;
        float bb = b2S[o], gg = g2S[o], ee = e2S[o];
        #pragma unroll
        for (int q = 0; q < 4; q++) {
            float2 v = *(float2*)&a2[i][q];
            float2 hv;
            hv.x = leaky(fmaf(v.x + bb, gg, ee));
            hv.y = leaky(fmaf(v.y + bb, gg, ee));
            *(float2*)(h2T + o*34 + pbase + 2*q) = hv;
        }
    }
    __syncthreads();

    // ---- layer 3: 128 -> 3 + residual ----
    if (tid < 96) {
        int pt = tid / 3, cc = tid - pt*3;
        float s0 = 0.f, s1 = 0.f;
        #pragma unroll 8
        for (int k = 0; k < 128; k += 2) {
            s0 = fmaf(h2T[k*34 + pt],     wf3S[k*3 + cc],     s0);
            s1 = fmaf(h2T[(k+1)*34 + pt], wf3S[(k+1)*3 + cc], s1);
        }
        int gp = p0 + pt;
        out[gp*3 + cc] = fmaf(0.1f, (s0 + s1) + bf3S[cc], x[gp*3 + cc]);
    }
}

// ---------------------------------------------------------------------------
extern "C" void kernel_launch(void* const* d_in, const int* in_sizes, int n_in,
                              void* d_out, int out_size)
{
    const float* x    = (const float*)d_in[0];
    const float* W1   = (const float*)d_in[1];
    const float* b1   = (const float*)d_in[2];
    const float* g1   = (const float*)d_in[3];
    const float* be1  = (const float*)d_in[4];
    const float* W2   = (const float*)d_in[5];
    const float* b2   = (const float*)d_in[6];
    const float* g2   = (const float*)d_in[7];
    const float* be2  = (const float*)d_in[8];
    const float* Ws1  = (const float*)d_in[9];
    const float* bs1  = (const float*)d_in[10];
    const float* Ws2  = (const float*)d_in[11];
    const float* bs2  = (const float*)d_in[12];
    const float* Wf1  = (const float*)d_in[13];
    const float* bf1  = (const float*)d_in[14];
    const float* gf1  = (const float*)d_in[15];
    const float* bef1 = (const float*)d_in[16];
    const float* Wf2  = (const float*)d_in[17];
    const float* bf2  = (const float*)d_in[18];
    const float* gf2  = (const float*)d_in[19];
    const float* bef2 = (const float*)d_in[20];
    const float* Wf3  = (const float*)d_in[21];
    const float* bf3  = (const float*)d_in[22];
    float* out = (float*)d_out;

    const int SM1 = 17540 * 4;   // k_pk shared bytes (prep layout dominates)
    const int SM4 = 25444 * 4;   // k_fuse shared bytes (~101.8KB)

    cudaFuncSetAttribute(k_pk,   cudaFuncAttributeMaxDynamicSharedMemorySize, SM1);
    cudaFuncSetAttribute(k_fuse, cudaFuncAttributeMaxDynamicSharedMemorySize, SM4);

    k_pk<<<NKNNB + NPREPB, 256, SM1>>>(x, W1, b1, g1, be1, W2, b2,
                                       Ws1, bs1, Ws2, bs2);
    k_fuse<<<PTS/PTB, 256, SM4>>>(x, g2, be2, Wf1, bf1, gf1, bef1,
                                  Wf2, bf2, gf2, bef2, Wf3, bf3, out);
}